// round 2
// baseline (speedup 1.0000x reference)
#include <cuda_runtime.h>
#include <math.h>

// ----------------------------------------------------------------------------
// IGNN / EGNN layer, GB300 (sm_103a)
//
// Inputs (metadata order = setup_inputs dict order):
//  0: x          [50000, 3]    f32
//  1: h          [50000, 128]  f32
//  2: edge_attr  [800000, 16]  f32
//  3: We1        [128, 273]    f32
//  4: be1        [128]         f32
//  5: We2        [128, 128]    f32
//  6: be2        [128]         f32
//  7: Wh1        [128, 256]    f32
//  8: bh1        [128]         f32
//  9: Wh2        [128, 128]    f32
// 10: bh2        [128]         f32
// 11: Wa         [1, 128]      f32
// 12: ba         [1]           f32
// 13: edge_index [2, 800000]   int32  (JAX default x64-disabled downcasts int64)
// out: node_attr [50000, 128]  f32
//
// Algebraic decomposition: e_in @ We1^T splits into
//   Ha[row] + Hb[col] + radial * w_r + edge_attr @ W1e^T   (+ be1)
// with Ha = h @ W1a^T, Hb = h @ W1b^T precomputed per NODE (50k rows)
// instead of per EDGE (800k rows): cuts MLP1 flops ~16x.
// ----------------------------------------------------------------------------

#define NN 50000
#define NE 800000
#define DH 128
#define DE 16
#define DM 128

// scratch (no allocations allowed -> device globals); align for float4 access
__device__ __align__(16) float g_Ha[(size_t)NN * DM];
__device__ __align__(16) float g_Hb[(size_t)NN * DM];
__device__ __align__(16) float g_msg[(size_t)NN * DM];

__device__ __forceinline__ float fsigmoid(float v) {
    return 1.0f / (1.0f + __expf(-v));
}

__device__ __forceinline__ void fma8(float acc[8], float a, const float* __restrict__ w) {
    float4 w0 = *(const float4*)(w);
    float4 w1 = *(const float4*)(w + 4);
    acc[0] += a * w0.x; acc[1] += a * w0.y; acc[2] += a * w0.z; acc[3] += a * w0.w;
    acc[4] += a * w1.x; acc[5] += a * w1.y; acc[6] += a * w1.z; acc[7] += a * w1.w;
}

// ---------------------------------------------------------------------------
// kernel 0: zero the message accumulator (needed every replay)
// ---------------------------------------------------------------------------
__global__ void zero_msg_kernel() {
    size_t i = (size_t)blockIdx.x * blockDim.x + threadIdx.x;
    size_t n4 = (size_t)NN * DM / 4;
    if (i < n4) ((float4*)g_msg)[i] = make_float4(0.f, 0.f, 0.f, 0.f);
}

// ---------------------------------------------------------------------------
// kernel 1: node precompute  Ha = h @ W1a^T,  Hb = h @ W1b^T
// ---------------------------------------------------------------------------
__global__ void __launch_bounds__(256, 1)
node_pre_kernel(const float* __restrict__ h, const float* __restrict__ We1) {
    extern __shared__ float sm[];
    float* W1aT = sm;               // 16384
    float* W1bT = sm + 16384;       // 16384
    float* hs   = sm + 32768;       // 16*129 = 2064

    const int tid = threadIdx.x;
    for (int idx = tid; idx < 128 * 128; idx += 256) {
        int k = idx >> 7, j = idx & 127;
        W1aT[j * 128 + k] = We1[k * 273 + j];
        W1bT[j * 128 + k] = We1[k * 273 + 128 + j];
    }

    const int g = tid >> 4, e = tid & 15, k0 = g * 8;

    for (int tile = blockIdx.x; tile < NN / 16; tile += gridDim.x) {
        const int base = tile * 16;
        __syncthreads();
        for (int idx = tid; idx < 16 * 128; idx += 256) {
            int ee = idx >> 7, j = idx & 127;
            hs[ee * 129 + j] = h[(size_t)(base + ee) * DH + j];
        }
        __syncthreads();

        float accA[8], accB[8];
#pragma unroll
        for (int r = 0; r < 8; r++) { accA[r] = 0.f; accB[r] = 0.f; }

#pragma unroll 8
        for (int j = 0; j < 128; j++) {
            float a = hs[e * 129 + j];
            fma8(accA, a, W1aT + j * 128 + k0);
            fma8(accB, a, W1bT + j * 128 + k0);
        }

        float* pa = g_Ha + (size_t)(base + e) * DM + k0;
        float* pb = g_Hb + (size_t)(base + e) * DM + k0;
        ((float4*)pa)[0] = make_float4(accA[0], accA[1], accA[2], accA[3]);
        ((float4*)pa)[1] = make_float4(accA[4], accA[5], accA[6], accA[7]);
        ((float4*)pb)[0] = make_float4(accB[0], accB[1], accB[2], accB[3]);
        ((float4*)pb)[1] = make_float4(accB[4], accB[5], accB[6], accB[7]);
    }
}

// ---------------------------------------------------------------------------
// kernel 2: edge kernel (the hot one)
// ---------------------------------------------------------------------------
__global__ void __launch_bounds__(256, 2)
edge_kernel(const float* __restrict__ x,
            const float* __restrict__ edge_attr,
            const float* __restrict__ We1,
            const float* __restrict__ be1,
            const float* __restrict__ We2,
            const float* __restrict__ be2,
            const float* __restrict__ Wa,
            const float* __restrict__ ba,
            const int* __restrict__ ei) {
    extern __shared__ float sm[];
    float* W2T  = sm;               // 16384
    float* W1eT = sm + 16384;       // 16*128 = 2048
    float* Wr   = sm + 18432;       // 128
    float* be1s = sm + 18560;       // 128
    float* be2s = sm + 18688;       // 128
    float* Was  = sm + 18816;       // 128
    float* eas  = sm + 18944;       // 16*17 = 272
    float* m1s  = sm + 19216;       // 16*129 = 2064
    float* red  = sm + 21280;       // 16*17 = 272
    float* attS = sm + 21552;       // 16
    float* radS = sm + 21568;       // 16
    int*   srow = (int*)(sm + 21584); // 16
    int*   scol = (int*)(sm + 21600); // 16
    // total 21616 floats = 86464 bytes

    const int tid = threadIdx.x;

    for (int idx = tid; idx < 128 * 128; idx += 256) {
        int k = idx >> 7, j = idx & 127;
        W2T[j * 128 + k] = We2[k * 128 + j];
    }
    for (int idx = tid; idx < 16 * 128; idx += 256) {
        int t = idx >> 7, k = idx & 127;
        W1eT[t * 128 + k] = We1[k * 273 + 257 + t]; // edge_attr cols are 257..272
    }
    for (int k = tid; k < 128; k += 256) {
        Wr[k]   = We1[k * 273 + 256];               // radial col is 256
        be1s[k] = be1[k];
        be2s[k] = be2[k];
        Was[k]  = Wa[k];
    }
    const float ba0 = ba[0];

    const int g = tid >> 4, e = tid & 15, k0 = g * 8;

    for (int tile = blockIdx.x; tile < NE / 16; tile += gridDim.x) {
        const int base = tile * 16;
        __syncthreads();  // protect smem reuse across tiles

        if (tid < 16) {
            int ee = tid;
            int r = ei[base + ee];
            int c = ei[NE + base + ee];
            srow[ee] = r;
            scol[ee] = c;
            float dx = x[(size_t)r * 3 + 0] - x[(size_t)c * 3 + 0];
            float dy = x[(size_t)r * 3 + 1] - x[(size_t)c * 3 + 1];
            float dz = x[(size_t)r * 3 + 2] - x[(size_t)c * 3 + 2];
            radS[ee] = sqrtf(dx * dx + dy * dy + dz * dz);
        }
        {
            int ee = tid >> 4, t = tid & 15;
            eas[ee * 17 + t] = edge_attr[(size_t)(base + ee) * DE + t];
        }
        __syncthreads();

        const int row = srow[e];
        const int col = scol[e];
        const float rad = radS[e];

        // --- stage 1: pre1 / m1 ---
        float acc[8];
        {
            const float4* pHa = (const float4*)(g_Ha + (size_t)row * DM + k0);
            const float4* pHb = (const float4*)(g_Hb + (size_t)col * DM + k0);
            float4 a0 = pHa[0], a1 = pHa[1];
            float4 b0 = pHb[0], b1 = pHb[1];
            acc[0] = a0.x + b0.x; acc[1] = a0.y + b0.y;
            acc[2] = a0.z + b0.z; acc[3] = a0.w + b0.w;
            acc[4] = a1.x + b1.x; acc[5] = a1.y + b1.y;
            acc[6] = a1.z + b1.z; acc[7] = a1.w + b1.w;
#pragma unroll
            for (int r = 0; r < 8; r++)
                acc[r] += be1s[k0 + r] + rad * Wr[k0 + r];
        }
#pragma unroll
        for (int t = 0; t < 16; t++) {
            float a = eas[e * 17 + t];
            fma8(acc, a, W1eT + t * 128 + k0);
        }
#pragma unroll
        for (int r = 0; r < 8; r++) {
            float v = acc[r];
            m1s[e * 129 + k0 + r] = v * fsigmoid(v);   // silu
        }
        __syncthreads();

        // --- stage 2: pre2 / m2 ---
        float acc2[8];
#pragma unroll
        for (int r = 0; r < 8; r++) acc2[r] = be2s[k0 + r];
#pragma unroll 16
        for (int j = 0; j < 128; j++) {
            float a = m1s[e * 129 + j];
            fma8(acc2, a, W2T + j * 128 + k0);
        }
        float m2[8];
        float p = 0.f;
#pragma unroll
        for (int r = 0; r < 8; r++) {
            float v = acc2[r];
            float mv = v * fsigmoid(v);                // silu
            m2[r] = mv;
            p += mv * Was[k0 + r];
        }
        red[e * 17 + g] = p;
        __syncthreads();

        if (tid < 16) {
            int ee = tid;
            float s = ba0;
#pragma unroll
            for (int gg = 0; gg < 16; gg++) s += red[ee * 17 + gg];
            attS[ee] = fsigmoid(s);
        }
        __syncthreads();

        const float av = attS[e];
        float* dst = g_msg + (size_t)row * DM + k0;
#pragma unroll
        for (int r = 0; r < 8; r++)
            atomicAdd(dst + r, m2[r] * av);
    }
}

// ---------------------------------------------------------------------------
// kernel 3: node post  out = h + silu([h, msg] @ Wh1^T + bh1) @ Wh2^T + bh2
// ---------------------------------------------------------------------------
__global__ void __launch_bounds__(256, 1)
node_post_kernel(const float* __restrict__ h,
                 const float* __restrict__ Wh1,
                 const float* __restrict__ bh1,
                 const float* __restrict__ Wh2,
                 const float* __restrict__ bh2,
                 float* __restrict__ out) {
    extern __shared__ float sm[];
    float* W1T = sm;                // 256*128 = 32768
    float* W2T = sm + 32768;        // 16384
    float* his = sm + 49152;        // 16*257 = 4112
    float* us  = sm + 53264;        // 16*129 = 2064
    float* b1s = sm + 55328;        // 128
    float* b2s = sm + 55456;        // 128
    // total 55584 floats = 222336 bytes

    const int tid = threadIdx.x;

    for (int idx = tid; idx < 256 * 128; idx += 256) {
        int k = idx >> 8, j = idx & 255;
        W1T[j * 128 + k] = Wh1[k * 256 + j];
    }
    for (int idx = tid; idx < 128 * 128; idx += 256) {
        int k = idx >> 7, j = idx & 127;
        W2T[j * 128 + k] = Wh2[k * 128 + j];
    }
    for (int k = tid; k < 128; k += 256) {
        b1s[k] = bh1[k];
        b2s[k] = bh2[k];
    }

    const int g = tid >> 4, e = tid & 15, k0 = g * 8;

    for (int tile = blockIdx.x; tile < NN / 16; tile += gridDim.x) {
        const int base = tile * 16;
        __syncthreads();
        for (int idx = tid; idx < 16 * 256; idx += 256) {
            int ee = idx >> 8, j = idx & 255;
            float v = (j < 128) ? h[(size_t)(base + ee) * DH + j]
                                : g_msg[(size_t)(base + ee) * DM + (j - 128)];
            his[ee * 257 + j] = v;
        }
        __syncthreads();

        float acc[8];
#pragma unroll
        for (int r = 0; r < 8; r++) acc[r] = b1s[k0 + r];
#pragma unroll 8
        for (int j = 0; j < 256; j++) {
            float a = his[e * 257 + j];
            fma8(acc, a, W1T + j * 128 + k0);
        }
#pragma unroll
        for (int r = 0; r < 8; r++) {
            float v = acc[r];
            us[e * 129 + k0 + r] = v * fsigmoid(v);   // silu
        }
        __syncthreads();

        float acc2[8];
#pragma unroll
        for (int r = 0; r < 8; r++) acc2[r] = b2s[k0 + r];
#pragma unroll 16
        for (int j = 0; j < 128; j++) {
            float a = us[e * 129 + j];
            fma8(acc2, a, W2T + j * 128 + k0);
        }

        float* po = out + (size_t)(base + e) * DH + k0;
        float4 o0 = make_float4(his[e * 257 + k0 + 0] + acc2[0],
                                his[e * 257 + k0 + 1] + acc2[1],
                                his[e * 257 + k0 + 2] + acc2[2],
                                his[e * 257 + k0 + 3] + acc2[3]);
        float4 o1 = make_float4(his[e * 257 + k0 + 4] + acc2[4],
                                his[e * 257 + k0 + 5] + acc2[5],
                                his[e * 257 + k0 + 6] + acc2[6],
                                his[e * 257 + k0 + 7] + acc2[7]);
        ((float4*)po)[0] = o0;
        ((float4*)po)[1] = o1;
    }
}

// ---------------------------------------------------------------------------
extern "C" void kernel_launch(void* const* d_in, const int* in_sizes, int n_in,
                              void* d_out, int out_size) {
    const float* x   = (const float*)d_in[0];
    const float* h   = (const float*)d_in[1];
    const float* ea  = (const float*)d_in[2];
    const float* We1 = (const float*)d_in[3];
    const float* be1 = (const float*)d_in[4];
    const float* We2 = (const float*)d_in[5];
    const float* be2 = (const float*)d_in[6];
    const float* Wh1 = (const float*)d_in[7];
    const float* bh1 = (const float*)d_in[8];
    const float* Wh2 = (const float*)d_in[9];
    const float* bh2 = (const float*)d_in[10];
    const float* Wa  = (const float*)d_in[11];
    const float* ba  = (const float*)d_in[12];
    const int*   ei  = (const int*)d_in[13];   // int32 (JAX x64 disabled)
    float* out = (float*)d_out;

    const int SM_PRE  = 34832 * 4;   // 139328 B
    const int SM_EDGE = 21616 * 4;   //  86464 B
    const int SM_POST = 55584 * 4;   // 222336 B

    cudaFuncSetAttribute(node_pre_kernel,
                         cudaFuncAttributeMaxDynamicSharedMemorySize, SM_PRE);
    cudaFuncSetAttribute(edge_kernel,
                         cudaFuncAttributeMaxDynamicSharedMemorySize, SM_EDGE);
    cudaFuncSetAttribute(node_post_kernel,
                         cudaFuncAttributeMaxDynamicSharedMemorySize, SM_POST);

    zero_msg_kernel<<<(NN * DM / 4 + 255) / 256, 256>>>();
    node_pre_kernel<<<148, 256, SM_PRE>>>(h, We1);
    edge_kernel<<<296, 256, SM_EDGE>>>(x, ea, We1, be1, We2, be2, Wa, ba, ei);
    node_post_kernel<<<148, 256, SM_POST>>>(h, Wh1, bh1, Wh2, bh2, out);
}

// round 4
// speedup vs baseline: 1.2744x; 1.2744x over previous
#include <cuda_runtime.h>
#include <math.h>

// ----------------------------------------------------------------------------
// IGNN / EGNN layer, GB300 (sm_103a) — round 4: R3 register blocking
// (2 items/thread, 16-32 FFMA per weight LDS.128 pair) + fixed first-tile
// smem race on bias init in node_post (preamble now fenced in every kernel).
//
// e_in @ We1^T decomposed as Ha[row] + Hb[col] + r*w_r + edge_attr @ W1e^T
// with Ha/Hb precomputed per node.  edge_index is int32.
// ----------------------------------------------------------------------------

#define NN 50000
#define NE 800000
#define DH 128
#define DE 16
#define DM 128

__device__ __align__(16) float g_Ha[(size_t)NN * DM];
__device__ __align__(16) float g_Hb[(size_t)NN * DM];
__device__ __align__(16) float g_msg[(size_t)NN * DM];

__device__ __forceinline__ float fsigmoid(float v) {
    return 1.0f / (1.0f + __expf(-v));
}

// 8 outputs for TWO independent items sharing the same weights
__device__ __forceinline__ void fma8x2(float a0c[8], float a1c[8], float a0, float a1,
                                       const float* __restrict__ w) {
    float4 w0 = *(const float4*)(w);
    float4 w1 = *(const float4*)(w + 4);
    a0c[0] += a0 * w0.x; a1c[0] += a1 * w0.x;
    a0c[1] += a0 * w0.y; a1c[1] += a1 * w0.y;
    a0c[2] += a0 * w0.z; a1c[2] += a1 * w0.z;
    a0c[3] += a0 * w0.w; a1c[3] += a1 * w0.w;
    a0c[4] += a0 * w1.x; a1c[4] += a1 * w1.x;
    a0c[5] += a0 * w1.y; a1c[5] += a1 * w1.y;
    a0c[6] += a0 * w1.z; a1c[6] += a1 * w1.z;
    a0c[7] += a0 * w1.w; a1c[7] += a1 * w1.w;
}

// ---------------------------------------------------------------------------
__global__ void zero_msg_kernel() {
    size_t i = (size_t)blockIdx.x * blockDim.x + threadIdx.x;
    size_t n4 = (size_t)NN * DM / 4;
    if (i < n4) ((float4*)g_msg)[i] = make_float4(0.f, 0.f, 0.f, 0.f);
}

// ---------------------------------------------------------------------------
// kernel 1: Ha = h @ W1a^T, Hb = h @ W1b^T.  32 nodes/tile, 2 nodes/thread.
// ---------------------------------------------------------------------------
__global__ void __launch_bounds__(256, 1)
node_pre_kernel(const float* __restrict__ h, const float* __restrict__ We1) {
    extern __shared__ float sm[];
    float* W1aT = sm;               // 16384
    float* W1bT = sm + 16384;       // 16384
    float* hs   = sm + 32768;       // 32*129 = 4128

    const int tid = threadIdx.x;
    for (int idx = tid; idx < 128 * 128; idx += 256) {
        int k = idx >> 7, j = idx & 127;
        W1aT[j * 128 + k] = We1[k * 273 + j];
        W1bT[j * 128 + k] = We1[k * 273 + 128 + j];
    }
    __syncthreads();   // fence preamble

    const int g = tid >> 4, e0 = tid & 15, e1 = e0 + 16, k0 = g * 8;
    const int ntiles = (NN + 31) / 32;

    for (int tile = blockIdx.x; tile < ntiles; tile += gridDim.x) {
        const int base = tile * 32;
        __syncthreads();
        for (int idx = tid; idx < 32 * 128; idx += 256) {
            int ee = idx >> 7, j = idx & 127;
            int node = base + ee;
            hs[ee * 129 + j] = (node < NN) ? h[(size_t)node * DH + j] : 0.f;
        }
        __syncthreads();

        float A0[8], A1[8], B0[8], B1[8];
#pragma unroll
        for (int r = 0; r < 8; r++) { A0[r] = A1[r] = B0[r] = B1[r] = 0.f; }

#pragma unroll 8
        for (int j = 0; j < 128; j++) {
            float a0 = hs[e0 * 129 + j];
            float a1 = hs[e1 * 129 + j];
            fma8x2(A0, A1, a0, a1, W1aT + j * 128 + k0);
            fma8x2(B0, B1, a0, a1, W1bT + j * 128 + k0);
        }

        if (base + e0 < NN) {
            float* pa = g_Ha + (size_t)(base + e0) * DM + k0;
            float* pb = g_Hb + (size_t)(base + e0) * DM + k0;
            ((float4*)pa)[0] = make_float4(A0[0], A0[1], A0[2], A0[3]);
            ((float4*)pa)[1] = make_float4(A0[4], A0[5], A0[6], A0[7]);
            ((float4*)pb)[0] = make_float4(B0[0], B0[1], B0[2], B0[3]);
            ((float4*)pb)[1] = make_float4(B0[4], B0[5], B0[6], B0[7]);
        }
        if (base + e1 < NN) {
            float* pa = g_Ha + (size_t)(base + e1) * DM + k0;
            float* pb = g_Hb + (size_t)(base + e1) * DM + k0;
            ((float4*)pa)[0] = make_float4(A1[0], A1[1], A1[2], A1[3]);
            ((float4*)pa)[1] = make_float4(A1[4], A1[5], A1[6], A1[7]);
            ((float4*)pb)[0] = make_float4(B1[0], B1[1], B1[2], B1[3]);
            ((float4*)pb)[1] = make_float4(B1[4], B1[5], B1[6], B1[7]);
        }
    }
}

// ---------------------------------------------------------------------------
// kernel 2: edge kernel.  32 edges/tile, 2 edges/thread.
// ---------------------------------------------------------------------------
__global__ void __launch_bounds__(256, 2)
edge_kernel(const float* __restrict__ x,
            const float* __restrict__ edge_attr,
            const float* __restrict__ We1,
            const float* __restrict__ be1,
            const float* __restrict__ We2,
            const float* __restrict__ be2,
            const float* __restrict__ Wa,
            const float* __restrict__ ba,
            const int* __restrict__ ei) {
    extern __shared__ float sm[];
    float* W2T  = sm;                 // 16384
    float* W1eT = sm + 16384;         // 2048
    float* Wr   = sm + 18432;         // 128
    float* be1s = sm + 18560;         // 128
    float* be2s = sm + 18688;         // 128
    float* Was  = sm + 18816;         // 128
    float* eas  = sm + 18944;         // 32*17 = 544
    float* m1s  = sm + 19488;         // 32*129 = 4128
    float* red  = sm + 23616;         // 32*17 = 544
    float* attS = sm + 24160;         // 32
    float* radS = sm + 24192;         // 32
    int*   srow = (int*)(sm + 24224); // 32
    int*   scol = (int*)(sm + 24256); // 32
    // total 24288 floats = 97152 B  -> 2 blocks/SM

    const int tid = threadIdx.x;

    for (int idx = tid; idx < 128 * 128; idx += 256) {
        int k = idx >> 7, j = idx & 127;
        W2T[j * 128 + k] = We2[k * 128 + j];
    }
    for (int idx = tid; idx < 16 * 128; idx += 256) {
        int t = idx >> 7, k = idx & 127;
        W1eT[t * 128 + k] = We1[k * 273 + 257 + t];     // edge_attr cols 257..272
    }
    for (int k = tid; k < 128; k += 256) {
        Wr[k]   = We1[k * 273 + 256];                   // radial col 256
        be1s[k] = be1[k];
        be2s[k] = be2[k];
        Was[k]  = Wa[k];
    }
    const float ba0 = ba[0];
    __syncthreads();   // fence preamble

    const int g = tid >> 4, e0 = tid & 15, e1 = e0 + 16, k0 = g * 8;

    for (int tile = blockIdx.x; tile < NE / 32; tile += gridDim.x) {
        const int base = tile * 32;
        __syncthreads();   // protect smem reuse across tiles

        if (tid < 32) {
            int ee = tid;
            int r = ei[base + ee];
            int c = ei[NE + base + ee];
            srow[ee] = r;
            scol[ee] = c;
            float dx = x[(size_t)r * 3 + 0] - x[(size_t)c * 3 + 0];
            float dy = x[(size_t)r * 3 + 1] - x[(size_t)c * 3 + 1];
            float dz = x[(size_t)r * 3 + 2] - x[(size_t)c * 3 + 2];
            radS[ee] = sqrtf(dx * dx + dy * dy + dz * dz);
        }
        for (int idx = tid; idx < 32 * 16; idx += 256) {
            int ee = idx >> 4, t = idx & 15;
            eas[ee * 17 + t] = edge_attr[(size_t)(base + ee) * DE + t];
        }
        __syncthreads();

        const int row0 = srow[e0], col0 = scol[e0];
        const int row1 = srow[e1], col1 = scol[e1];
        const float rad0 = radS[e0], rad1 = radS[e1];

        // --- stage 1 ---
        float acc0[8], acc1[8];
        {
            const float4* pHa0 = (const float4*)(g_Ha + (size_t)row0 * DM + k0);
            const float4* pHb0 = (const float4*)(g_Hb + (size_t)col0 * DM + k0);
            const float4* pHa1 = (const float4*)(g_Ha + (size_t)row1 * DM + k0);
            const float4* pHb1 = (const float4*)(g_Hb + (size_t)col1 * DM + k0);
            float4 a00 = pHa0[0], a01 = pHa0[1], b00 = pHb0[0], b01 = pHb0[1];
            float4 a10 = pHa1[0], a11 = pHa1[1], b10 = pHb1[0], b11 = pHb1[1];
            acc0[0] = a00.x + b00.x; acc0[1] = a00.y + b00.y;
            acc0[2] = a00.z + b00.z; acc0[3] = a00.w + b00.w;
            acc0[4] = a01.x + b01.x; acc0[5] = a01.y + b01.y;
            acc0[6] = a01.z + b01.z; acc0[7] = a01.w + b01.w;
            acc1[0] = a10.x + b10.x; acc1[1] = a10.y + b10.y;
            acc1[2] = a10.z + b10.z; acc1[3] = a10.w + b10.w;
            acc1[4] = a11.x + b11.x; acc1[5] = a11.y + b11.y;
            acc1[6] = a11.z + b11.z; acc1[7] = a11.w + b11.w;
#pragma unroll
            for (int r = 0; r < 8; r++) {
                float bb = be1s[k0 + r], wr = Wr[k0 + r];
                acc0[r] += bb + rad0 * wr;
                acc1[r] += bb + rad1 * wr;
            }
        }
#pragma unroll
        for (int t = 0; t < 16; t++) {
            float a0 = eas[e0 * 17 + t];
            float a1 = eas[e1 * 17 + t];
            fma8x2(acc0, acc1, a0, a1, W1eT + t * 128 + k0);
        }
#pragma unroll
        for (int r = 0; r < 8; r++) {
            float v0 = acc0[r], v1 = acc1[r];
            m1s[e0 * 129 + k0 + r] = v0 * fsigmoid(v0);
            m1s[e1 * 129 + k0 + r] = v1 * fsigmoid(v1);
        }
        __syncthreads();

        // --- stage 2 ---
        float c0[8], c1[8];
#pragma unroll
        for (int r = 0; r < 8; r++) { c0[r] = c1[r] = be2s[k0 + r]; }
#pragma unroll 8
        for (int j = 0; j < 128; j++) {
            float a0 = m1s[e0 * 129 + j];
            float a1 = m1s[e1 * 129 + j];
            fma8x2(c0, c1, a0, a1, W2T + j * 128 + k0);
        }
        float m20[8], m21[8];
        float p0 = 0.f, p1 = 0.f;
#pragma unroll
        for (int r = 0; r < 8; r++) {
            float wv = Was[k0 + r];
            float v0 = c0[r], v1 = c1[r];
            float mv0 = v0 * fsigmoid(v0);
            float mv1 = v1 * fsigmoid(v1);
            m20[r] = mv0; m21[r] = mv1;
            p0 += mv0 * wv; p1 += mv1 * wv;
        }
        red[e0 * 17 + g] = p0;
        red[e1 * 17 + g] = p1;
        __syncthreads();

        if (tid < 32) {
            int ee = tid;
            float s = ba0;
#pragma unroll
            for (int gg = 0; gg < 16; gg++) s += red[ee * 17 + gg];
            attS[ee] = fsigmoid(s);
        }
        __syncthreads();

        const float av0 = attS[e0];
        const float av1 = attS[e1];
        float* dst0 = g_msg + (size_t)row0 * DM + k0;
        float* dst1 = g_msg + (size_t)row1 * DM + k0;
#pragma unroll
        for (int r = 0; r < 8; r++) {
            atomicAdd(dst0 + r, m20[r] * av0);
            atomicAdd(dst1 + r, m21[r] * av1);
        }
    }
}

// ---------------------------------------------------------------------------
// kernel 3: node post.  32 nodes/tile, 2 nodes/thread, weights in 2 K-passes.
// ---------------------------------------------------------------------------
__global__ void __launch_bounds__(256, 1)
node_post_kernel(const float* __restrict__ h,
                 const float* __restrict__ Wh1,
                 const float* __restrict__ bh1,
                 const float* __restrict__ Wh2,
                 const float* __restrict__ bh2,
                 float* __restrict__ out) {
    extern __shared__ float sm[];
    float* W1T = sm;                 // 256*128 = 32768
    float* W2T = sm + 32768;         // 16384
    float* buf = sm + 49152;         // 32*129 = 4128
    float* b1s = sm + 53280;         // 128
    float* b2s = sm + 53408;         // 128
    // total 53536 floats = 214144 B

    const int tid = threadIdx.x;

    for (int idx = tid; idx < 256 * 128; idx += 256) {
        int k = idx >> 8, j = idx & 255;
        W1T[j * 128 + k] = Wh1[k * 256 + j];
    }
    for (int idx = tid; idx < 128 * 128; idx += 256) {
        int k = idx >> 7, j = idx & 127;
        W2T[j * 128 + k] = Wh2[k * 128 + j];
    }
    for (int k = tid; k < 128; k += 256) {
        b1s[k] = bh1[k];
        b2s[k] = bh2[k];
    }
    __syncthreads();   // fence preamble (R3 bug: bias was read before this)

    const int g = tid >> 4, e0 = tid & 15, e1 = e0 + 16, k0 = g * 8;
    const int ntiles = (NN + 31) / 32;

    for (int tile = blockIdx.x; tile < ntiles; tile += gridDim.x) {
        const int base = tile * 32;

        // pass A: h
        __syncthreads();
        for (int idx = tid; idx < 32 * 128; idx += 256) {
            int ee = idx >> 7, j = idx & 127;
            int node = base + ee;
            buf[ee * 129 + j] = (node < NN) ? h[(size_t)node * DH + j] : 0.f;
        }
        __syncthreads();

        float acc0[8], acc1[8];
#pragma unroll
        for (int r = 0; r < 8; r++) { acc0[r] = acc1[r] = b1s[k0 + r]; }

#pragma unroll 8
        for (int j = 0; j < 128; j++) {
            float a0 = buf[e0 * 129 + j];
            float a1 = buf[e1 * 129 + j];
            fma8x2(acc0, acc1, a0, a1, W1T + j * 128 + k0);
        }

        // pass B: msg
        __syncthreads();
        for (int idx = tid; idx < 32 * 128; idx += 256) {
            int ee = idx >> 7, j = idx & 127;
            int node = base + ee;
            buf[ee * 129 + j] = (node < NN) ? g_msg[(size_t)node * DM + j] : 0.f;
        }
        __syncthreads();
#pragma unroll 8
        for (int j = 0; j < 128; j++) {
            float a0 = buf[e0 * 129 + j];
            float a1 = buf[e1 * 129 + j];
            fma8x2(acc0, acc1, a0, a1, W1T + (j + 128) * 128 + k0);
        }

        // silu -> reuse buf
        __syncthreads();
#pragma unroll
        for (int r = 0; r < 8; r++) {
            float v0 = acc0[r], v1 = acc1[r];
            buf[e0 * 129 + k0 + r] = v0 * fsigmoid(v0);
            buf[e1 * 129 + k0 + r] = v1 * fsigmoid(v1);
        }
        __syncthreads();

        // GEMM2 + residual
        float c0[8], c1[8];
#pragma unroll
        for (int r = 0; r < 8; r++) { c0[r] = c1[r] = b2s[k0 + r]; }
#pragma unroll 8
        for (int j = 0; j < 128; j++) {
            float a0 = buf[e0 * 129 + j];
            float a1 = buf[e1 * 129 + j];
            fma8x2(c0, c1, a0, a1, W2T + j * 128 + k0);
        }

        if (base + e0 < NN) {
            const float4* ph = (const float4*)(h + (size_t)(base + e0) * DH + k0);
            float4 h0 = ph[0], h1 = ph[1];
            float* po = out + (size_t)(base + e0) * DH + k0;
            ((float4*)po)[0] = make_float4(h0.x + c0[0], h0.y + c0[1], h0.z + c0[2], h0.w + c0[3]);
            ((float4*)po)[1] = make_float4(h1.x + c0[4], h1.y + c0[5], h1.z + c0[6], h1.w + c0[7]);
        }
        if (base + e1 < NN) {
            const float4* ph = (const float4*)(h + (size_t)(base + e1) * DH + k0);
            float4 h0 = ph[0], h1 = ph[1];
            float* po = out + (size_t)(base + e1) * DH + k0;
            ((float4*)po)[0] = make_float4(h0.x + c1[0], h0.y + c1[1], h0.z + c1[2], h0.w + c1[3]);
            ((float4*)po)[1] = make_float4(h1.x + c1[4], h1.y + c1[5], h1.z + c1[6], h1.w + c1[7]);
        }
    }
}

// ---------------------------------------------------------------------------
extern "C" void kernel_launch(void* const* d_in, const int* in_sizes, int n_in,
                              void* d_out, int out_size) {
    const float* x   = (const float*)d_in[0];
    const float* h   = (const float*)d_in[1];
    const float* ea  = (const float*)d_in[2];
    const float* We1 = (const float*)d_in[3];
    const float* be1 = (const float*)d_in[4];
    const float* We2 = (const float*)d_in[5];
    const float* be2 = (const float*)d_in[6];
    const float* Wh1 = (const float*)d_in[7];
    const float* bh1 = (const float*)d_in[8];
    const float* Wh2 = (const float*)d_in[9];
    const float* bh2 = (const float*)d_in[10];
    const float* Wa  = (const float*)d_in[11];
    const float* ba  = (const float*)d_in[12];
    const int*   ei  = (const int*)d_in[13];   // int32
    float* out = (float*)d_out;

    const int SM_PRE  = 36896 * 4;   // 147584 B
    const int SM_EDGE = 24288 * 4;   //  97152 B
    const int SM_POST = 53536 * 4;   // 214144 B

    cudaFuncSetAttribute(node_pre_kernel,
                         cudaFuncAttributeMaxDynamicSharedMemorySize, SM_PRE);
    cudaFuncSetAttribute(edge_kernel,
                         cudaFuncAttributeMaxDynamicSharedMemorySize, SM_EDGE);
    cudaFuncSetAttribute(node_post_kernel,
                         cudaFuncAttributeMaxDynamicSharedMemorySize, SM_POST);

    zero_msg_kernel<<<(NN * DM / 4 + 255) / 256, 256>>>();
    node_pre_kernel<<<148, 256, SM_PRE>>>(h, We1);
    edge_kernel<<<296, 256, SM_EDGE>>>(x, ea, We1, be1, We2, be2, Wa, ba, ei);
    node_post_kernel<<<148, 256, SM_POST>>>(h, Wh1, bh1, Wh2, bh2, out);
}

// round 6
// speedup vs baseline: 1.8264x; 1.4332x over previous
#include <cuda_runtime.h>
#include <cuda_bf16.h>
#include <math.h>
#include <stdint.h>

// ----------------------------------------------------------------------------
// IGNN / EGNN layer, GB300 (sm_103a, built as sm_103 -> no tcgen05).
// Round 6: edge MLP stage-2 GEMM on mma.sync bf16 HMMA (m16n8k16),
// vectorized red.global.add.v2.f32 scatter. Node kernels unchanged (R4).
//
// e_in @ We1^T decomposed as Ha[row] + Hb[col] + r*w_r + edge_attr @ W1e^T,
// Ha/Hb precomputed per node.  edge_index is int32.
// ----------------------------------------------------------------------------

#define NN 50000
#define NE 800000
#define DH 128
#define DE 16
#define DM 128

__device__ __align__(16) float g_Ha[(size_t)NN * DM];
__device__ __align__(16) float g_Hb[(size_t)NN * DM];
__device__ __align__(16) float g_msg[(size_t)NN * DM];

__device__ __forceinline__ float fsigmoid(float v) {
    return 1.0f / (1.0f + __expf(-v));
}

__device__ __forceinline__ void fma8x2(float a0c[8], float a1c[8], float a0, float a1,
                                       const float* __restrict__ w) {
    float4 w0 = *(const float4*)(w);
    float4 w1 = *(const float4*)(w + 4);
    a0c[0] += a0 * w0.x; a1c[0] += a1 * w0.x;
    a0c[1] += a0 * w0.y; a1c[1] += a1 * w0.y;
    a0c[2] += a0 * w0.z; a1c[2] += a1 * w0.z;
    a0c[3] += a0 * w0.w; a1c[3] += a1 * w0.w;
    a0c[4] += a0 * w1.x; a1c[4] += a1 * w1.x;
    a0c[5] += a0 * w1.y; a1c[5] += a1 * w1.y;
    a0c[6] += a0 * w1.z; a1c[6] += a1 * w1.z;
    a0c[7] += a0 * w1.w; a1c[7] += a1 * w1.w;
}

__device__ __forceinline__ uint32_t smem_to_u32(const void* smem_ptr) {
    uint32_t addr;
    asm("{ .reg .u64 tmp; cvta.to.shared.u64 tmp, %1; cvt.u32.u64 %0, tmp; }"
        : "=r"(addr) : "l"(smem_ptr));
    return addr;
}

__device__ __forceinline__ void ldmatrix_x4(uint32_t& r0, uint32_t& r1,
                                            uint32_t& r2, uint32_t& r3, uint32_t addr) {
    asm volatile("ldmatrix.sync.aligned.m8n8.x4.shared.b16 {%0,%1,%2,%3}, [%4];"
                 : "=r"(r0), "=r"(r1), "=r"(r2), "=r"(r3) : "r"(addr));
}
__device__ __forceinline__ void ldmatrix_x2(uint32_t& r0, uint32_t& r1, uint32_t addr) {
    asm volatile("ldmatrix.sync.aligned.m8n8.x2.shared.b16 {%0,%1}, [%2];"
                 : "=r"(r0), "=r"(r1) : "r"(addr));
}
__device__ __forceinline__ void mma_bf16(float d[4], const uint32_t a[4],
                                         const uint32_t b[2], const float c[4]) {
    asm volatile(
        "mma.sync.aligned.m16n8k16.row.col.f32.bf16.bf16.f32 "
        "{%0,%1,%2,%3}, {%4,%5,%6,%7}, {%8,%9}, {%10,%11,%12,%13};"
        : "=f"(d[0]), "=f"(d[1]), "=f"(d[2]), "=f"(d[3])
        : "r"(a[0]), "r"(a[1]), "r"(a[2]), "r"(a[3]),
          "r"(b[0]), "r"(b[1]),
          "f"(c[0]), "f"(c[1]), "f"(c[2]), "f"(c[3]));
}
__device__ __forceinline__ void red_v2(float* addr, float v0, float v1) {
    asm volatile("red.global.add.v2.f32 [%0], {%1, %2};"
                 :: "l"(addr), "f"(v0), "f"(v1) : "memory");
}

// ---------------------------------------------------------------------------
__global__ void zero_msg_kernel() {
    size_t i = (size_t)blockIdx.x * blockDim.x + threadIdx.x;
    size_t n4 = (size_t)NN * DM / 4;
    if (i < n4) ((float4*)g_msg)[i] = make_float4(0.f, 0.f, 0.f, 0.f);
}

// ---------------------------------------------------------------------------
// kernel 1: Ha = h @ W1a^T, Hb = h @ W1b^T.  (unchanged from R4)
// ---------------------------------------------------------------------------
__global__ void __launch_bounds__(256, 1)
node_pre_kernel(const float* __restrict__ h, const float* __restrict__ We1) {
    extern __shared__ float sm[];
    float* W1aT = sm;               // 16384
    float* W1bT = sm + 16384;       // 16384
    float* hs   = sm + 32768;       // 32*129 = 4128

    const int tid = threadIdx.x;
    for (int idx = tid; idx < 128 * 128; idx += 256) {
        int k = idx >> 7, j = idx & 127;
        W1aT[j * 128 + k] = We1[k * 273 + j];
        W1bT[j * 128 + k] = We1[k * 273 + 128 + j];
    }
    __syncthreads();

    const int g = tid >> 4, e0 = tid & 15, e1 = e0 + 16, k0 = g * 8;
    const int ntiles = (NN + 31) / 32;

    for (int tile = blockIdx.x; tile < ntiles; tile += gridDim.x) {
        const int base = tile * 32;
        __syncthreads();
        for (int idx = tid; idx < 32 * 128; idx += 256) {
            int ee = idx >> 7, j = idx & 127;
            int node = base + ee;
            hs[ee * 129 + j] = (node < NN) ? h[(size_t)node * DH + j] : 0.f;
        }
        __syncthreads();

        float A0[8], A1[8], B0[8], B1[8];
#pragma unroll
        for (int r = 0; r < 8; r++) { A0[r] = A1[r] = B0[r] = B1[r] = 0.f; }

#pragma unroll 8
        for (int j = 0; j < 128; j++) {
            float a0 = hs[e0 * 129 + j];
            float a1 = hs[e1 * 129 + j];
            fma8x2(A0, A1, a0, a1, W1aT + j * 128 + k0);
            fma8x2(B0, B1, a0, a1, W1bT + j * 128 + k0);
        }

        if (base + e0 < NN) {
            float* pa = g_Ha + (size_t)(base + e0) * DM + k0;
            float* pb = g_Hb + (size_t)(base + e0) * DM + k0;
            ((float4*)pa)[0] = make_float4(A0[0], A0[1], A0[2], A0[3]);
            ((float4*)pa)[1] = make_float4(A0[4], A0[5], A0[6], A0[7]);
            ((float4*)pb)[0] = make_float4(B0[0], B0[1], B0[2], B0[3]);
            ((float4*)pb)[1] = make_float4(B0[4], B0[5], B0[6], B0[7]);
        }
        if (base + e1 < NN) {
            float* pa = g_Ha + (size_t)(base + e1) * DM + k0;
            float* pb = g_Hb + (size_t)(base + e1) * DM + k0;
            ((float4*)pa)[0] = make_float4(A1[0], A1[1], A1[2], A1[3]);
            ((float4*)pa)[1] = make_float4(A1[4], A1[5], A1[6], A1[7]);
            ((float4*)pb)[0] = make_float4(B1[0], B1[1], B1[2], B1[3]);
            ((float4*)pb)[1] = make_float4(B1[4], B1[5], B1[6], B1[7]);
        }
    }
}

// ---------------------------------------------------------------------------
// kernel 2: edge kernel, HMMA stage 2.
// tile = 128 edges, 256 threads (8 warps), 2 CTAs/SM.
//
// SMEM bytes:
//   [0]      m1s  : 128 x 136 bf16 (row stride 272B, ldmatrix-friendly) 34816
//   [34816]  W2s  : 128 x 136 bf16 (We2 as [n][k])                      34816
//   [69632]  W1eT : 16 x 128 f32                                         8192
//   [77824]  Wr / [78336] be1s / [78848] be2s / [79360] Was : 128 f32 each
//   [79872]  eas  : 128 x 17 f32                                         8704
//   [88576]  radS : 128 f32 / [89088] srow / [89600] scol : 128 i32
//   total 90112 B
// ---------------------------------------------------------------------------
#define EB_M1    0
#define EB_W2    34816
#define EB_W1ET  69632
#define EB_WR    77824
#define EB_BE1   78336
#define EB_BE2   78848
#define EB_WAS   79360
#define EB_EAS   79872
#define EB_RAD   88576
#define EB_SROW  89088
#define EB_SCOL  89600
#define EB_TOTAL 90112

#define M1_STRIDE 272   // bytes per m1/W2 row (136 bf16)

__global__ void __launch_bounds__(256, 2)
edge_kernel(const float* __restrict__ x,
            const float* __restrict__ edge_attr,
            const float* __restrict__ We1,
            const float* __restrict__ be1,
            const float* __restrict__ We2,
            const float* __restrict__ be2,
            const float* __restrict__ Wa,
            const float* __restrict__ ba,
            const int* __restrict__ ei) {
    extern __shared__ __align__(16) char smraw[];
    float* W1eT = (float*)(smraw + EB_W1ET);
    float* Wr   = (float*)(smraw + EB_WR);
    float* be1s = (float*)(smraw + EB_BE1);
    float* be2s = (float*)(smraw + EB_BE2);
    float* Was  = (float*)(smraw + EB_WAS);
    float* eas  = (float*)(smraw + EB_EAS);
    float* radS = (float*)(smraw + EB_RAD);
    int*   srow = (int*)(smraw + EB_SROW);
    int*   scol = (int*)(smraw + EB_SCOL);

    const uint32_t smem_u32 = smem_to_u32(smraw);
    const int tid  = threadIdx.x;
    const int warp = tid >> 5;
    const int lane = tid & 31;

    // ---- preamble ----
    for (int idx = tid; idx < 128 * 128; idx += 256) {
        int n = idx >> 7, k = idx & 127;
        *(__nv_bfloat16*)(smraw + EB_W2 + n * M1_STRIDE + k * 2) =
            __float2bfloat16(We2[n * 128 + k]);
    }
    for (int idx = tid; idx < 16 * 128; idx += 256) {
        int t = idx >> 7, k = idx & 127;
        W1eT[t * 128 + k] = We1[k * 273 + 257 + t];     // edge_attr cols 257..272
    }
    for (int k = tid; k < 128; k += 256) {
        Wr[k]   = We1[k * 273 + 256];                   // radial col 256
        be1s[k] = be1[k];
        be2s[k] = be2[k];
        Was[k]  = Wa[k];
    }
    const float ba0 = ba[0];
    __syncthreads();

    // ldmatrix lane base addresses
    // A (m1): warp owns rows m0..m0+15.  x4 matrices:
    //   lanes 0-7  -> row m0+l,       col k0
    //   lanes 8-15 -> row m0+8+(l&7), col k0
    //   lanes16-23 -> row m0+(l&7),   col k0+8
    //   lanes24-31 -> row m0+8+(l&7), col k0+8
    const int m0 = warp * 16;
    const int arow = m0 + (lane & 7) + ((lane >> 3) & 1) * 8;
    const uint32_t a_base = smem_u32 + EB_M1 + (uint32_t)arow * M1_STRIDE
                          + ((lane >> 4) & 1) * 16;
    // B (We2 [n][k]): x2 matrices (lanes 0-15; replicate for 16-31):
    //   lanes 0-7  -> row n0+l,      col k0
    //   lanes 8-15 -> row n0+(l&7),  col k0+8
    const int bl = lane & 15;
    const uint32_t b_base = smem_u32 + EB_W2 + (uint32_t)(bl & 7) * M1_STRIDE
                          + ((bl >> 3) & 1) * 16;

    const int g = tid >> 4, e0b = tid & 15, k0c = g * 8;
    const int tig = lane & 3, grp = lane >> 2;   // mma thread-in-group / group

    for (int tile = blockIdx.x; tile < NE / 128; tile += gridDim.x) {
        const int base = tile * 128;
        __syncthreads();   // protect smem reuse across tiles

        // ---- per-edge loads ----
        if (tid < 128) {
            int r = ei[base + tid];
            int c = ei[NE + base + tid];
            srow[tid] = r;
            scol[tid] = c;
            float dx = x[(size_t)r * 3 + 0] - x[(size_t)c * 3 + 0];
            float dy = x[(size_t)r * 3 + 1] - x[(size_t)c * 3 + 1];
            float dz = x[(size_t)r * 3 + 2] - x[(size_t)c * 3 + 2];
            radS[tid] = sqrtf(dx * dx + dy * dy + dz * dz);
        }
        for (int idx = tid; idx < 128 * 16; idx += 256) {
            int ee = idx >> 4, t = idx & 15;
            eas[ee * 17 + t] = edge_attr[(size_t)(base + ee) * DE + t];
        }
        __syncthreads();

        // ---- stage 1: m1 = silu(Ha[row]+Hb[col]+rad*wr+be1 + ea@W1e^T) -> bf16 ----
#pragma unroll
        for (int s = 0; s < 4; s++) {
            const int le0 = s * 32 + e0b;
            const int le1 = le0 + 16;
            const int row0 = srow[le0], col0 = scol[le0];
            const int row1 = srow[le1], col1 = scol[le1];
            const float rad0 = radS[le0], rad1 = radS[le1];

            float acc0[8], acc1[8];
            {
                const float4* pHa0 = (const float4*)(g_Ha + (size_t)row0 * DM + k0c);
                const float4* pHb0 = (const float4*)(g_Hb + (size_t)col0 * DM + k0c);
                const float4* pHa1 = (const float4*)(g_Ha + (size_t)row1 * DM + k0c);
                const float4* pHb1 = (const float4*)(g_Hb + (size_t)col1 * DM + k0c);
                float4 a00 = pHa0[0], a01 = pHa0[1], b00 = pHb0[0], b01 = pHb0[1];
                float4 a10 = pHa1[0], a11 = pHa1[1], b10 = pHb1[0], b11 = pHb1[1];
                acc0[0] = a00.x + b00.x; acc0[1] = a00.y + b00.y;
                acc0[2] = a00.z + b00.z; acc0[3] = a00.w + b00.w;
                acc0[4] = a01.x + b01.x; acc0[5] = a01.y + b01.y;
                acc0[6] = a01.z + b01.z; acc0[7] = a01.w + b01.w;
                acc1[0] = a10.x + b10.x; acc1[1] = a10.y + b10.y;
                acc1[2] = a10.z + b10.z; acc1[3] = a10.w + b10.w;
                acc1[4] = a11.x + b11.x; acc1[5] = a11.y + b11.y;
                acc1[6] = a11.z + b11.z; acc1[7] = a11.w + b11.w;
#pragma unroll
                for (int r = 0; r < 8; r++) {
                    float bb = be1s[k0c + r], wr = Wr[k0c + r];
                    acc0[r] += bb + rad0 * wr;
                    acc1[r] += bb + rad1 * wr;
                }
            }
#pragma unroll
            for (int t = 0; t < 16; t++) {
                float a0 = eas[le0 * 17 + t];
                float a1 = eas[le1 * 17 + t];
                fma8x2(acc0, acc1, a0, a1, W1eT + t * 128 + k0c);
            }
            uint32_t p0[4], p1[4];
#pragma unroll
            for (int r = 0; r < 4; r++) {
                float v00 = acc0[2 * r], v01 = acc0[2 * r + 1];
                float v10 = acc1[2 * r], v11 = acc1[2 * r + 1];
                __nv_bfloat162 q0 = __floats2bfloat162_rn(v00 * fsigmoid(v00), v01 * fsigmoid(v01));
                __nv_bfloat162 q1 = __floats2bfloat162_rn(v10 * fsigmoid(v10), v11 * fsigmoid(v11));
                p0[r] = *(uint32_t*)&q0;
                p1[r] = *(uint32_t*)&q1;
            }
            *(uint4*)(smraw + EB_M1 + le0 * M1_STRIDE + k0c * 2) =
                make_uint4(p0[0], p0[1], p0[2], p0[3]);
            *(uint4*)(smraw + EB_M1 + le1 * M1_STRIDE + k0c * 2) =
                make_uint4(p1[0], p1[1], p1[2], p1[3]);
        }
        __syncthreads();

        // ---- stage 2: HMMA  D[16x128] = m1[16x128] @ We2^T ----
        float acc[16][4];
#pragma unroll
        for (int nt = 0; nt < 16; nt++)
#pragma unroll
            for (int r = 0; r < 4; r++) acc[nt][r] = 0.f;

#pragma unroll
        for (int k = 0; k < 8; k++) {
            uint32_t a[4];
            ldmatrix_x4(a[0], a[1], a[2], a[3], a_base + (uint32_t)k * 32);
#pragma unroll
            for (int nt = 0; nt < 16; nt++) {
                uint32_t b[2];
                ldmatrix_x2(b[0], b[1],
                            b_base + (uint32_t)nt * (8 * M1_STRIDE) + (uint32_t)k * 32);
                mma_bf16(acc[nt], a, b, acc[nt]);
            }
        }

        // ---- epilogue (register-resident) ----
        // thread owns rows (m0+grp, m0+grp+8), cols nt*8 + tig*2, +1
        float pr0 = 0.f, pr1 = 0.f;
#pragma unroll
        for (int nt = 0; nt < 16; nt++) {
            const int c0 = nt * 8 + tig * 2;
            float2 bb = *(float2*)&be2s[c0];
            float2 wa = *(float2*)&Was[c0];
            float v0 = acc[nt][0] + bb.x;
            float v1 = acc[nt][1] + bb.y;
            float v2 = acc[nt][2] + bb.x;
            float v3 = acc[nt][3] + bb.y;
            float s0 = v0 * fsigmoid(v0);
            float s1 = v1 * fsigmoid(v1);
            float s2 = v2 * fsigmoid(v2);
            float s3 = v3 * fsigmoid(v3);
            acc[nt][0] = s0; acc[nt][1] = s1; acc[nt][2] = s2; acc[nt][3] = s3;
            pr0 += s0 * wa.x + s1 * wa.y;
            pr1 += s2 * wa.x + s3 * wa.y;
        }
        pr0 += __shfl_xor_sync(0xFFFFFFFF, pr0, 1);
        pr0 += __shfl_xor_sync(0xFFFFFFFF, pr0, 2);
        pr1 += __shfl_xor_sync(0xFFFFFFFF, pr1, 1);
        pr1 += __shfl_xor_sync(0xFFFFFFFF, pr1, 2);
        const float att0 = fsigmoid(pr0 + ba0);
        const float att1 = fsigmoid(pr1 + ba0);

        const int node0 = srow[m0 + grp];
        const int node1 = srow[m0 + grp + 8];
        float* d0 = g_msg + (size_t)node0 * DM;
        float* d1 = g_msg + (size_t)node1 * DM;
#pragma unroll
        for (int nt = 0; nt < 16; nt++) {
            const int c0 = nt * 8 + tig * 2;
            red_v2(d0 + c0, acc[nt][0] * att0, acc[nt][1] * att0);
            red_v2(d1 + c0, acc[nt][2] * att1, acc[nt][3] * att1);
        }
    }
}

// ---------------------------------------------------------------------------
// kernel 3: node post.  (unchanged from R4)
// ---------------------------------------------------------------------------
__global__ void __launch_bounds__(256, 1)
node_post_kernel(const float* __restrict__ h,
                 const float* __restrict__ Wh1,
                 const float* __restrict__ bh1,
                 const float* __restrict__ Wh2,
                 const float* __restrict__ bh2,
                 float* __restrict__ out) {
    extern __shared__ float sm[];
    float* W1T = sm;                 // 32768
    float* W2T = sm + 32768;         // 16384
    float* buf = sm + 49152;         // 32*129 = 4128
    float* b1s = sm + 53280;         // 128
    float* b2s = sm + 53408;         // 128

    const int tid = threadIdx.x;

    for (int idx = tid; idx < 256 * 128; idx += 256) {
        int k = idx >> 8, j = idx & 255;
        W1T[j * 128 + k] = Wh1[k * 256 + j];
    }
    for (int idx = tid; idx < 128 * 128; idx += 256) {
        int k = idx >> 7, j = idx & 127;
        W2T[j * 128 + k] = Wh2[k * 128 + j];
    }
    for (int k = tid; k < 128; k += 256) {
        b1s[k] = bh1[k];
        b2s[k] = bh2[k];
    }
    __syncthreads();

    const int g = tid >> 4, e0 = tid & 15, e1 = e0 + 16, k0 = g * 8;
    const int ntiles = (NN + 31) / 32;

    for (int tile = blockIdx.x; tile < ntiles; tile += gridDim.x) {
        const int base = tile * 32;

        __syncthreads();
        for (int idx = tid; idx < 32 * 128; idx += 256) {
            int ee = idx >> 7, j = idx & 127;
            int node = base + ee;
            buf[ee * 129 + j] = (node < NN) ? h[(size_t)node * DH + j] : 0.f;
        }
        __syncthreads();

        float acc0[8], acc1[8];
#pragma unroll
        for (int r = 0; r < 8; r++) { acc0[r] = acc1[r] = b1s[k0 + r]; }

#pragma unroll 8
        for (int j = 0; j < 128; j++) {
            float a0 = buf[e0 * 129 + j];
            float a1 = buf[e1 * 129 + j];
            fma8x2(acc0, acc1, a0, a1, W1T + j * 128 + k0);
        }

        __syncthreads();
        for (int idx = tid; idx < 32 * 128; idx += 256) {
            int ee = idx >> 7, j = idx & 127;
            int node = base + ee;
            buf[ee * 129 + j] = (node < NN) ? g_msg[(size_t)node * DM + j] : 0.f;
        }
        __syncthreads();
#pragma unroll 8
        for (int j = 0; j < 128; j++) {
            float a0 = buf[e0 * 129 + j];
            float a1 = buf[e1 * 129 + j];
            fma8x2(acc0, acc1, a0, a1, W1T + (j + 128) * 128 + k0);
        }

        __syncthreads();
#pragma unroll
        for (int r = 0; r < 8; r++) {
            float v0 = acc0[r], v1 = acc1[r];
            buf[e0 * 129 + k0 + r] = v0 * fsigmoid(v0);
            buf[e1 * 129 + k0 + r] = v1 * fsigmoid(v1);
        }
        __syncthreads();

        float c0[8], c1[8];
#pragma unroll
        for (int r = 0; r < 8; r++) { c0[r] = c1[r] = b2s[k0 + r]; }
#pragma unroll 8
        for (int j = 0; j < 128; j++) {
            float a0 = buf[e0 * 129 + j];
            float a1 = buf[e1 * 129 + j];
            fma8x2(c0, c1, a0, a1, W2T + j * 128 + k0);
        }

        if (base + e0 < NN) {
            const float4* ph4 = (const float4*)(h + (size_t)(base + e0) * DH + k0);
            float4 h0 = ph4[0], h1 = ph4[1];
            float* po = out + (size_t)(base + e0) * DH + k0;
            ((float4*)po)[0] = make_float4(h0.x + c0[0], h0.y + c0[1], h0.z + c0[2], h0.w + c0[3]);
            ((float4*)po)[1] = make_float4(h1.x + c0[4], h1.y + c0[5], h1.z + c0[6], h1.w + c0[7]);
        }
        if (base + e1 < NN) {
            const float4* ph4 = (const float4*)(h + (size_t)(base + e1) * DH + k0);
            float4 h0 = ph4[0], h1 = ph4[1];
            float* po = out + (size_t)(base + e1) * DH + k0;
            ((float4*)po)[0] = make_float4(h0.x + c1[0], h0.y + c1[1], h0.z + c1[2], h0.w + c1[3]);
            ((float4*)po)[1] = make_float4(h1.x + c1[4], h1.y + c1[5], h1.z + c1[6], h1.w + c1[7]);
        }
    }
}

// ---------------------------------------------------------------------------
extern "C" void kernel_launch(void* const* d_in, const int* in_sizes, int n_in,
                              void* d_out, int out_size) {
    const float* x   = (const float*)d_in[0];
    const float* h   = (const float*)d_in[1];
    const float* ea  = (const float*)d_in[2];
    const float* We1 = (const float*)d_in[3];
    const float* be1 = (const float*)d_in[4];
    const float* We2 = (const float*)d_in[5];
    const float* be2 = (const float*)d_in[6];
    const float* Wh1 = (const float*)d_in[7];
    const float* bh1 = (const float*)d_in[8];
    const float* Wh2 = (const float*)d_in[9];
    const float* bh2 = (const float*)d_in[10];
    const float* Wa  = (const float*)d_in[11];
    const float* ba  = (const float*)d_in[12];
    const int*   ei  = (const int*)d_in[13];   // int32
    float* out = (float*)d_out;

    const int SM_PRE  = 36896 * 4;   // 147584 B
    const int SM_EDGE = EB_TOTAL;    //  90112 B
    const int SM_POST = 53536 * 4;   // 214144 B

    cudaFuncSetAttribute(node_pre_kernel,
                         cudaFuncAttributeMaxDynamicSharedMemorySize, SM_PRE);
    cudaFuncSetAttribute(edge_kernel,
                         cudaFuncAttributeMaxDynamicSharedMemorySize, SM_EDGE);
    cudaFuncSetAttribute(node_post_kernel,
                         cudaFuncAttributeMaxDynamicSharedMemorySize, SM_POST);

    zero_msg_kernel<<<(NN * DM / 4 + 255) / 256, 256>>>();
    node_pre_kernel<<<148, 256, SM_PRE>>>(h, We1);
    edge_kernel<<<296, 256, SM_EDGE>>>(x, ea, We1, be1, We2, be2, Wa, ba, ei);
    node_post_kernel<<<148, 256, SM_POST>>>(h, Wh1, bh1, Wh2, bh2, out);
}

// round 7
// speedup vs baseline: 2.2862x; 1.2517x over previous
#include <cuda_runtime.h>
#include <cuda_bf16.h>
#include <math.h>
#include <stdint.h>

// ----------------------------------------------------------------------------
// IGNN / EGNN layer, GB300 (sm_103a built as sm_103 -> mma.sync, no tcgen05).
// Round 7: node_pre and node_post moved onto the same m16n8k16 bf16 HMMA
// machinery proven in R6's edge kernel. Edge kernel unchanged from R6.
// ----------------------------------------------------------------------------

#define NN 50000
#define NE 800000
#define DH 128
#define DE 16
#define DM 128

__device__ __align__(16) float g_Ha[(size_t)NN * DM];
__device__ __align__(16) float g_Hb[(size_t)NN * DM];
__device__ __align__(16) float g_msg[(size_t)NN * DM];

__device__ __forceinline__ float fsigmoid(float v) {
    return 1.0f / (1.0f + __expf(-v));
}

__device__ __forceinline__ void fma8x2(float a0c[8], float a1c[8], float a0, float a1,
                                       const float* __restrict__ w) {
    float4 w0 = *(const float4*)(w);
    float4 w1 = *(const float4*)(w + 4);
    a0c[0] += a0 * w0.x; a1c[0] += a1 * w0.x;
    a0c[1] += a0 * w0.y; a1c[1] += a1 * w0.y;
    a0c[2] += a0 * w0.z; a1c[2] += a1 * w0.z;
    a0c[3] += a0 * w0.w; a1c[3] += a1 * w0.w;
    a0c[4] += a0 * w1.x; a1c[4] += a1 * w1.x;
    a0c[5] += a0 * w1.y; a1c[5] += a1 * w1.y;
    a0c[6] += a0 * w1.z; a1c[6] += a1 * w1.z;
    a0c[7] += a0 * w1.w; a1c[7] += a1 * w1.w;
}

__device__ __forceinline__ uint32_t smem_to_u32(const void* smem_ptr) {
    uint32_t addr;
    asm("{ .reg .u64 tmp; cvta.to.shared.u64 tmp, %1; cvt.u32.u64 %0, tmp; }"
        : "=r"(addr) : "l"(smem_ptr));
    return addr;
}

__device__ __forceinline__ void ldmatrix_x4(uint32_t& r0, uint32_t& r1,
                                            uint32_t& r2, uint32_t& r3, uint32_t addr) {
    asm volatile("ldmatrix.sync.aligned.m8n8.x4.shared.b16 {%0,%1,%2,%3}, [%4];"
                 : "=r"(r0), "=r"(r1), "=r"(r2), "=r"(r3) : "r"(addr));
}
__device__ __forceinline__ void ldmatrix_x2(uint32_t& r0, uint32_t& r1, uint32_t addr) {
    asm volatile("ldmatrix.sync.aligned.m8n8.x2.shared.b16 {%0,%1}, [%2];"
                 : "=r"(r0), "=r"(r1) : "r"(addr));
}
__device__ __forceinline__ void mma_bf16(float d[4], const uint32_t a[4],
                                         const uint32_t b[2], const float c[4]) {
    asm volatile(
        "mma.sync.aligned.m16n8k16.row.col.f32.bf16.bf16.f32 "
        "{%0,%1,%2,%3}, {%4,%5,%6,%7}, {%8,%9}, {%10,%11,%12,%13};"
        : "=f"(d[0]), "=f"(d[1]), "=f"(d[2]), "=f"(d[3])
        : "r"(a[0]), "r"(a[1]), "r"(a[2]), "r"(a[3]),
          "r"(b[0]), "r"(b[1]),
          "f"(c[0]), "f"(c[1]), "f"(c[2]), "f"(c[3]));
}
__device__ __forceinline__ void red_v2(float* addr, float v0, float v1) {
    asm volatile("red.global.add.v2.f32 [%0], {%1, %2};"
                 :: "l"(addr), "f"(v0), "f"(v1) : "memory");
}

// pack float4 -> two bf16x2 words
__device__ __forceinline__ uint2 pack_bf16x4(float4 v) {
    __nv_bfloat162 lo = __floats2bfloat162_rn(v.x, v.y);
    __nv_bfloat162 hi = __floats2bfloat162_rn(v.z, v.w);
    uint2 r;
    r.x = *(uint32_t*)&lo;
    r.y = *(uint32_t*)&hi;
    return r;
}

// ---------------------------------------------------------------------------
__global__ void zero_msg_kernel() {
    size_t i = (size_t)blockIdx.x * blockDim.x + threadIdx.x;
    size_t n4 = (size_t)NN * DM / 4;
    if (i < n4) ((float4*)g_msg)[i] = make_float4(0.f, 0.f, 0.f, 0.f);
}

// ---------------------------------------------------------------------------
// kernel 1 (HMMA): Ha = h @ W1a^T, Hb = h @ W1b^T.
// tile = 128 nodes, 8 warps.  A = h bf16 [128 x 136], B = W1a/W1b bf16 [n][k].
// smem: A 34816 | WA 34816 | WB 34816  = 104448 B  -> 2 CTAs/SM
// ---------------------------------------------------------------------------
#define NP_A   0
#define NP_WA  34816
#define NP_WB  69632
#define NP_TOTAL 104448
#define RS 272   // row stride bytes for 128-col bf16 tiles (136 bf16)

__global__ void __launch_bounds__(256, 2)
node_pre_kernel(const float* __restrict__ h, const float* __restrict__ We1) {
    extern __shared__ __align__(16) char smraw[];
    const uint32_t smem_u32 = smem_to_u32(smraw);
    const int tid  = threadIdx.x;
    const int warp = tid >> 5;
    const int lane = tid & 31;

    // preamble: W1a/W1b -> bf16 [n][k]
    for (int idx = tid; idx < 128 * 128; idx += 256) {
        int n = idx >> 7, k = idx & 127;
        *(__nv_bfloat16*)(smraw + NP_WA + n * RS + k * 2) =
            __float2bfloat16(We1[n * 273 + k]);
        *(__nv_bfloat16*)(smraw + NP_WB + n * RS + k * 2) =
            __float2bfloat16(We1[n * 273 + 128 + k]);
    }
    __syncthreads();

    const int m0 = warp * 16;
    const int arow = m0 + (lane & 7) + ((lane >> 3) & 1) * 8;
    const uint32_t a_base  = smem_u32 + NP_A + (uint32_t)arow * RS + ((lane >> 4) & 1) * 16;
    const int bl = lane & 15;
    const uint32_t ba_base = smem_u32 + NP_WA + (uint32_t)(bl & 7) * RS + ((bl >> 3) & 1) * 16;
    const uint32_t bb_base = smem_u32 + NP_WB + (uint32_t)(bl & 7) * RS + ((bl >> 3) & 1) * 16;

    const int tig = lane & 3, grp = lane >> 2;
    const int ntiles = (NN + 127) / 128;

    for (int tile = blockIdx.x; tile < ntiles; tile += gridDim.x) {
        const int base = tile * 128;
        __syncthreads();
        // h tile -> A bf16 (float4 loads, 8B bf16x4 stores)
        for (int idx = tid; idx < 128 * 32; idx += 256) {
            int r = idx >> 5, j4 = (idx & 31) * 4;
            int node = base + r;
            float4 v = (node < NN) ? *(const float4*)&h[(size_t)node * DH + j4]
                                   : make_float4(0.f, 0.f, 0.f, 0.f);
            *(uint2*)(smraw + NP_A + r * RS + j4 * 2) = pack_bf16x4(v);
        }
        __syncthreads();

        const int node0 = base + m0 + grp;
        const int node1 = node0 + 8;

        // GEMM A -> Ha
        {
            float acc[16][4];
#pragma unroll
            for (int nt = 0; nt < 16; nt++)
#pragma unroll
                for (int r = 0; r < 4; r++) acc[nt][r] = 0.f;
#pragma unroll
            for (int k = 0; k < 8; k++) {
                uint32_t a[4];
                ldmatrix_x4(a[0], a[1], a[2], a[3], a_base + (uint32_t)k * 32);
#pragma unroll
                for (int nt = 0; nt < 16; nt++) {
                    uint32_t b[2];
                    ldmatrix_x2(b[0], b[1], ba_base + (uint32_t)nt * (8 * RS) + (uint32_t)k * 32);
                    mma_bf16(acc[nt], a, b, acc[nt]);
                }
            }
#pragma unroll
            for (int nt = 0; nt < 16; nt++) {
                const int c0 = nt * 8 + tig * 2;
                if (node0 < NN) *(float2*)&g_Ha[(size_t)node0 * DM + c0] =
                    make_float2(acc[nt][0], acc[nt][1]);
                if (node1 < NN) *(float2*)&g_Ha[(size_t)node1 * DM + c0] =
                    make_float2(acc[nt][2], acc[nt][3]);
            }
        }
        // GEMM B -> Hb
        {
            float acc[16][4];
#pragma unroll
            for (int nt = 0; nt < 16; nt++)
#pragma unroll
                for (int r = 0; r < 4; r++) acc[nt][r] = 0.f;
#pragma unroll
            for (int k = 0; k < 8; k++) {
                uint32_t a[4];
                ldmatrix_x4(a[0], a[1], a[2], a[3], a_base + (uint32_t)k * 32);
#pragma unroll
                for (int nt = 0; nt < 16; nt++) {
                    uint32_t b[2];
                    ldmatrix_x2(b[0], b[1], bb_base + (uint32_t)nt * (8 * RS) + (uint32_t)k * 32);
                    mma_bf16(acc[nt], a, b, acc[nt]);
                }
            }
#pragma unroll
            for (int nt = 0; nt < 16; nt++) {
                const int c0 = nt * 8 + tig * 2;
                if (node0 < NN) *(float2*)&g_Hb[(size_t)node0 * DM + c0] =
                    make_float2(acc[nt][0], acc[nt][1]);
                if (node1 < NN) *(float2*)&g_Hb[(size_t)node1 * DM + c0] =
                    make_float2(acc[nt][2], acc[nt][3]);
            }
        }
    }
}

// ---------------------------------------------------------------------------
// kernel 2: edge kernel, HMMA stage 2.  (unchanged from R6)
// ---------------------------------------------------------------------------
#define EB_M1    0
#define EB_W2    34816
#define EB_W1ET  69632
#define EB_WR    77824
#define EB_BE1   78336
#define EB_BE2   78848
#define EB_WAS   79360
#define EB_EAS   79872
#define EB_RAD   88576
#define EB_SROW  89088
#define EB_SCOL  89600
#define EB_TOTAL 90112

#define M1_STRIDE 272

__global__ void __launch_bounds__(256, 2)
edge_kernel(const float* __restrict__ x,
            const float* __restrict__ edge_attr,
            const float* __restrict__ We1,
            const float* __restrict__ be1,
            const float* __restrict__ We2,
            const float* __restrict__ be2,
            const float* __restrict__ Wa,
            const float* __restrict__ ba,
            const int* __restrict__ ei) {
    extern __shared__ __align__(16) char smraw[];
    float* W1eT = (float*)(smraw + EB_W1ET);
    float* Wr   = (float*)(smraw + EB_WR);
    float* be1s = (float*)(smraw + EB_BE1);
    float* be2s = (float*)(smraw + EB_BE2);
    float* Was  = (float*)(smraw + EB_WAS);
    float* eas  = (float*)(smraw + EB_EAS);
    float* radS = (float*)(smraw + EB_RAD);
    int*   srow = (int*)(smraw + EB_SROW);
    int*   scol = (int*)(smraw + EB_SCOL);

    const uint32_t smem_u32 = smem_to_u32(smraw);
    const int tid  = threadIdx.x;
    const int warp = tid >> 5;
    const int lane = tid & 31;

    for (int idx = tid; idx < 128 * 128; idx += 256) {
        int n = idx >> 7, k = idx & 127;
        *(__nv_bfloat16*)(smraw + EB_W2 + n * M1_STRIDE + k * 2) =
            __float2bfloat16(We2[n * 128 + k]);
    }
    for (int idx = tid; idx < 16 * 128; idx += 256) {
        int t = idx >> 7, k = idx & 127;
        W1eT[t * 128 + k] = We1[k * 273 + 257 + t];
    }
    for (int k = tid; k < 128; k += 256) {
        Wr[k]   = We1[k * 273 + 256];
        be1s[k] = be1[k];
        be2s[k] = be2[k];
        Was[k]  = Wa[k];
    }
    const float ba0 = ba[0];
    __syncthreads();

    const int m0 = warp * 16;
    const int arow = m0 + (lane & 7) + ((lane >> 3) & 1) * 8;
    const uint32_t a_base = smem_u32 + EB_M1 + (uint32_t)arow * M1_STRIDE
                          + ((lane >> 4) & 1) * 16;
    const int bl = lane & 15;
    const uint32_t b_base = smem_u32 + EB_W2 + (uint32_t)(bl & 7) * M1_STRIDE
                          + ((bl >> 3) & 1) * 16;

    const int g = tid >> 4, e0b = tid & 15, k0c = g * 8;
    const int tig = lane & 3, grp = lane >> 2;

    for (int tile = blockIdx.x; tile < NE / 128; tile += gridDim.x) {
        const int base = tile * 128;
        __syncthreads();

        if (tid < 128) {
            int r = ei[base + tid];
            int c = ei[NE + base + tid];
            srow[tid] = r;
            scol[tid] = c;
            float dx = x[(size_t)r * 3 + 0] - x[(size_t)c * 3 + 0];
            float dy = x[(size_t)r * 3 + 1] - x[(size_t)c * 3 + 1];
            float dz = x[(size_t)r * 3 + 2] - x[(size_t)c * 3 + 2];
            radS[tid] = sqrtf(dx * dx + dy * dy + dz * dz);
        }
        for (int idx = tid; idx < 128 * 16; idx += 256) {
            int ee = idx >> 4, t = idx & 15;
            eas[ee * 17 + t] = edge_attr[(size_t)(base + ee) * DE + t];
        }
        __syncthreads();

#pragma unroll
        for (int s = 0; s < 4; s++) {
            const int le0 = s * 32 + e0b;
            const int le1 = le0 + 16;
            const int row0 = srow[le0], col0 = scol[le0];
            const int row1 = srow[le1], col1 = scol[le1];
            const float rad0 = radS[le0], rad1 = radS[le1];

            float acc0[8], acc1[8];
            {
                const float4* pHa0 = (const float4*)(g_Ha + (size_t)row0 * DM + k0c);
                const float4* pHb0 = (const float4*)(g_Hb + (size_t)col0 * DM + k0c);
                const float4* pHa1 = (const float4*)(g_Ha + (size_t)row1 * DM + k0c);
                const float4* pHb1 = (const float4*)(g_Hb + (size_t)col1 * DM + k0c);
                float4 a00 = pHa0[0], a01 = pHa0[1], b00 = pHb0[0], b01 = pHb0[1];
                float4 a10 = pHa1[0], a11 = pHa1[1], b10 = pHb1[0], b11 = pHb1[1];
                acc0[0] = a00.x + b00.x; acc0[1] = a00.y + b00.y;
                acc0[2] = a00.z + b00.z; acc0[3] = a00.w + b00.w;
                acc0[4] = a01.x + b01.x; acc0[5] = a01.y + b01.y;
                acc0[6] = a01.z + b01.z; acc0[7] = a01.w + b01.w;
                acc1[0] = a10.x + b10.x; acc1[1] = a10.y + b10.y;
                acc1[2] = a10.z + b10.z; acc1[3] = a10.w + b10.w;
                acc1[4] = a11.x + b11.x; acc1[5] = a11.y + b11.y;
                acc1[6] = a11.z + b11.z; acc1[7] = a11.w + b11.w;
#pragma unroll
                for (int r = 0; r < 8; r++) {
                    float bb = be1s[k0c + r], wr = Wr[k0c + r];
                    acc0[r] += bb + rad0 * wr;
                    acc1[r] += bb + rad1 * wr;
                }
            }
#pragma unroll
            for (int t = 0; t < 16; t++) {
                float a0 = eas[le0 * 17 + t];
                float a1 = eas[le1 * 17 + t];
                fma8x2(acc0, acc1, a0, a1, W1eT + t * 128 + k0c);
            }
            uint32_t p0[4], p1[4];
#pragma unroll
            for (int r = 0; r < 4; r++) {
                float v00 = acc0[2 * r], v01 = acc0[2 * r + 1];
                float v10 = acc1[2 * r], v11 = acc1[2 * r + 1];
                __nv_bfloat162 q0 = __floats2bfloat162_rn(v00 * fsigmoid(v00), v01 * fsigmoid(v01));
                __nv_bfloat162 q1 = __floats2bfloat162_rn(v10 * fsigmoid(v10), v11 * fsigmoid(v11));
                p0[r] = *(uint32_t*)&q0;
                p1[r] = *(uint32_t*)&q1;
            }
            *(uint4*)(smraw + EB_M1 + le0 * M1_STRIDE + k0c * 2) =
                make_uint4(p0[0], p0[1], p0[2], p0[3]);
            *(uint4*)(smraw + EB_M1 + le1 * M1_STRIDE + k0c * 2) =
                make_uint4(p1[0], p1[1], p1[2], p1[3]);
        }
        __syncthreads();

        float acc[16][4];
#pragma unroll
        for (int nt = 0; nt < 16; nt++)
#pragma unroll
            for (int r = 0; r < 4; r++) acc[nt][r] = 0.f;

#pragma unroll
        for (int k = 0; k < 8; k++) {
            uint32_t a[4];
            ldmatrix_x4(a[0], a[1], a[2], a[3], a_base + (uint32_t)k * 32);
#pragma unroll
            for (int nt = 0; nt < 16; nt++) {
                uint32_t b[2];
                ldmatrix_x2(b[0], b[1],
                            b_base + (uint32_t)nt * (8 * M1_STRIDE) + (uint32_t)k * 32);
                mma_bf16(acc[nt], a, b, acc[nt]);
            }
        }

        float pr0 = 0.f, pr1 = 0.f;
#pragma unroll
        for (int nt = 0; nt < 16; nt++) {
            const int c0 = nt * 8 + tig * 2;
            float2 bb = *(float2*)&be2s[c0];
            float2 wa = *(float2*)&Was[c0];
            float v0 = acc[nt][0] + bb.x;
            float v1 = acc[nt][1] + bb.y;
            float v2 = acc[nt][2] + bb.x;
            float v3 = acc[nt][3] + bb.y;
            float s0 = v0 * fsigmoid(v0);
            float s1 = v1 * fsigmoid(v1);
            float s2 = v2 * fsigmoid(v2);
            float s3 = v3 * fsigmoid(v3);
            acc[nt][0] = s0; acc[nt][1] = s1; acc[nt][2] = s2; acc[nt][3] = s3;
            pr0 += s0 * wa.x + s1 * wa.y;
            pr1 += s2 * wa.x + s3 * wa.y;
        }
        pr0 += __shfl_xor_sync(0xFFFFFFFF, pr0, 1);
        pr0 += __shfl_xor_sync(0xFFFFFFFF, pr0, 2);
        pr1 += __shfl_xor_sync(0xFFFFFFFF, pr1, 1);
        pr1 += __shfl_xor_sync(0xFFFFFFFF, pr1, 2);
        const float att0 = fsigmoid(pr0 + ba0);
        const float att1 = fsigmoid(pr1 + ba0);

        const int node0 = srow[m0 + grp];
        const int node1 = srow[m0 + grp + 8];
        float* d0 = g_msg + (size_t)node0 * DM;
        float* d1 = g_msg + (size_t)node1 * DM;
#pragma unroll
        for (int nt = 0; nt < 16; nt++) {
            const int c0 = nt * 8 + tig * 2;
            red_v2(d0 + c0, acc[nt][0] * att0, acc[nt][1] * att0);
            red_v2(d1 + c0, acc[nt][2] * att1, acc[nt][3] * att1);
        }
    }
}

// ---------------------------------------------------------------------------
// kernel 3 (HMMA): out = h + silu([h,msg] @ Wh1^T + bh1) @ Wh2^T + bh2
// tile = 128 nodes, 8 warps.
// smem: A [128x264 bf16, stride 528] 67584 | W1 [128x264] 67584
//       W2 [128x136] 34816 | U [128x136] 34816 | b1 512 | b2 512  = 205824 B
// ---------------------------------------------------------------------------
#define PO_A   0
#define PO_W1  67584
#define PO_W2  135168
#define PO_U   169984
#define PO_B1  204800
#define PO_B2  205312
#define PO_TOTAL 205824
#define RS2 528   // row stride for 256-col bf16 tiles (264 bf16)

__global__ void __launch_bounds__(256, 1)
node_post_kernel(const float* __restrict__ h,
                 const float* __restrict__ Wh1,
                 const float* __restrict__ bh1,
                 const float* __restrict__ Wh2,
                 const float* __restrict__ bh2,
                 float* __restrict__ out) {
    extern __shared__ __align__(16) char smraw[];
    float* b1s = (float*)(smraw + PO_B1);
    float* b2s = (float*)(smraw + PO_B2);

    const uint32_t smem_u32 = smem_to_u32(smraw);
    const int tid  = threadIdx.x;
    const int warp = tid >> 5;
    const int lane = tid & 31;

    // preamble: Wh1 -> W1 bf16 [n][k 0..255], Wh2 -> W2 bf16 [n][k 0..127]
    for (int idx = tid; idx < 128 * 64; idx += 256) {
        int n = idx >> 6, k4 = (idx & 63) * 4;
        float4 v = *(const float4*)&Wh1[(size_t)n * 256 + k4];
        *(uint2*)(smraw + PO_W1 + n * RS2 + k4 * 2) = pack_bf16x4(v);
    }
    for (int idx = tid; idx < 128 * 32; idx += 256) {
        int n = idx >> 5, k4 = (idx & 31) * 4;
        float4 v = *(const float4*)&Wh2[(size_t)n * 128 + k4];
        *(uint2*)(smraw + PO_W2 + n * RS + k4 * 2) = pack_bf16x4(v);
    }
    for (int k = tid; k < 128; k += 256) {
        b1s[k] = bh1[k];
        b2s[k] = bh2[k];
    }
    __syncthreads();

    const int m0 = warp * 16;
    const int arow = m0 + (lane & 7) + ((lane >> 3) & 1) * 8;
    const uint32_t a1_base = smem_u32 + PO_A + (uint32_t)arow * RS2 + ((lane >> 4) & 1) * 16;
    const uint32_t a2_base = smem_u32 + PO_U + (uint32_t)arow * RS  + ((lane >> 4) & 1) * 16;
    const int bl = lane & 15;
    const uint32_t b1_base = smem_u32 + PO_W1 + (uint32_t)(bl & 7) * RS2 + ((bl >> 3) & 1) * 16;
    const uint32_t b2_base = smem_u32 + PO_W2 + (uint32_t)(bl & 7) * RS  + ((bl >> 3) & 1) * 16;

    const int tig = lane & 3, grp = lane >> 2;
    const int ntiles = (NN + 127) / 128;

    for (int tile = blockIdx.x; tile < ntiles; tile += gridDim.x) {
        const int base = tile * 128;
        __syncthreads();
        // A = [h | msg] bf16
        for (int idx = tid; idx < 128 * 32; idx += 256) {
            int r = idx >> 5, j4 = (idx & 31) * 4;
            int node = base + r;
            float4 vh = (node < NN) ? *(const float4*)&h[(size_t)node * DH + j4]
                                    : make_float4(0.f, 0.f, 0.f, 0.f);
            float4 vm = (node < NN) ? *(const float4*)&g_msg[(size_t)node * DM + j4]
                                    : make_float4(0.f, 0.f, 0.f, 0.f);
            *(uint2*)(smraw + PO_A + r * RS2 + j4 * 2)         = pack_bf16x4(vh);
            *(uint2*)(smraw + PO_A + r * RS2 + 256 + j4 * 2)   = pack_bf16x4(vm);
        }
        __syncthreads();

        // GEMM1: K=256
        float acc[16][4];
#pragma unroll
        for (int nt = 0; nt < 16; nt++)
#pragma unroll
            for (int r = 0; r < 4; r++) acc[nt][r] = 0.f;
#pragma unroll
        for (int k = 0; k < 16; k++) {
            uint32_t a[4];
            ldmatrix_x4(a[0], a[1], a[2], a[3], a1_base + (uint32_t)k * 32);
#pragma unroll
            for (int nt = 0; nt < 16; nt++) {
                uint32_t b[2];
                ldmatrix_x2(b[0], b[1], b1_base + (uint32_t)nt * (8 * RS2) + (uint32_t)k * 32);
                mma_bf16(acc[nt], a, b, acc[nt]);
            }
        }
        // silu -> U (bf16x2 per thread per nt per row)
#pragma unroll
        for (int nt = 0; nt < 16; nt++) {
            const int c0 = nt * 8 + tig * 2;
            float2 bb = *(float2*)&b1s[c0];
            float v0 = acc[nt][0] + bb.x;
            float v1 = acc[nt][1] + bb.y;
            float v2 = acc[nt][2] + bb.x;
            float v3 = acc[nt][3] + bb.y;
            __nv_bfloat162 q0 = __floats2bfloat162_rn(v0 * fsigmoid(v0), v1 * fsigmoid(v1));
            __nv_bfloat162 q1 = __floats2bfloat162_rn(v2 * fsigmoid(v2), v3 * fsigmoid(v3));
            *(uint32_t*)(smraw + PO_U + (m0 + grp) * RS + c0 * 2)     = *(uint32_t*)&q0;
            *(uint32_t*)(smraw + PO_U + (m0 + grp + 8) * RS + c0 * 2) = *(uint32_t*)&q1;
        }
        __syncthreads();

        // GEMM2: K=128
#pragma unroll
        for (int nt = 0; nt < 16; nt++)
#pragma unroll
            for (int r = 0; r < 4; r++) acc[nt][r] = 0.f;
#pragma unroll
        for (int k = 0; k < 8; k++) {
            uint32_t a[4];
            ldmatrix_x4(a[0], a[1], a[2], a[3], a2_base + (uint32_t)k * 32);
#pragma unroll
            for (int nt = 0; nt < 16; nt++) {
                uint32_t b[2];
                ldmatrix_x2(b[0], b[1], b2_base + (uint32_t)nt * (8 * RS) + (uint32_t)k * 32);
                mma_bf16(acc[nt], a, b, acc[nt]);
            }
        }

        // epilogue: out = h + acc + bh2
        const int node0 = base + m0 + grp;
        const int node1 = node0 + 8;
#pragma unroll
        for (int nt = 0; nt < 16; nt++) {
            const int c0 = nt * 8 + tig * 2;
            float2 bb = *(float2*)&b2s[c0];
            if (node0 < NN) {
                float2 hv = *(const float2*)&h[(size_t)node0 * DH + c0];
                *(float2*)&out[(size_t)node0 * DH + c0] =
                    make_float2(hv.x + acc[nt][0] + bb.x, hv.y + acc[nt][1] + bb.y);
            }
            if (node1 < NN) {
                float2 hv = *(const float2*)&h[(size_t)node1 * DH + c0];
                *(float2*)&out[(size_t)node1 * DH + c0] =
                    make_float2(hv.x + acc[nt][2] + bb.x, hv.y + acc[nt][3] + bb.y);
            }
        }
    }
}

// ---------------------------------------------------------------------------
extern "C" void kernel_launch(void* const* d_in, const int* in_sizes, int n_in,
                              void* d_out, int out_size) {
    const float* x   = (const float*)d_in[0];
    const float* h   = (const float*)d_in[1];
    const float* ea  = (const float*)d_in[2];
    const float* We1 = (const float*)d_in[3];
    const float* be1 = (const float*)d_in[4];
    const float* We2 = (const float*)d_in[5];
    const float* be2 = (const float*)d_in[6];
    const float* Wh1 = (const float*)d_in[7];
    const float* bh1 = (const float*)d_in[8];
    const float* Wh2 = (const float*)d_in[9];
    const float* bh2 = (const float*)d_in[10];
    const float* Wa  = (const float*)d_in[11];
    const float* ba  = (const float*)d_in[12];
    const int*   ei  = (const int*)d_in[13];   // int32
    float* out = (float*)d_out;

    cudaFuncSetAttribute(node_pre_kernel,
                         cudaFuncAttributeMaxDynamicSharedMemorySize, NP_TOTAL);
    cudaFuncSetAttribute(edge_kernel,
                         cudaFuncAttributeMaxDynamicSharedMemorySize, EB_TOTAL);
    cudaFuncSetAttribute(node_post_kernel,
                         cudaFuncAttributeMaxDynamicSharedMemorySize, PO_TOTAL);

    zero_msg_kernel<<<(NN * DM / 4 + 255) / 256, 256>>>();
    node_pre_kernel<<<296, 256, NP_TOTAL>>>(h, We1);
    edge_kernel<<<296, 256, EB_TOTAL>>>(x, ea, We1, be1, We2, be2, Wa, ba, ei);
    node_post_kernel<<<148, 256, PO_TOTAL>>>(h, Wh1, bh1, Wh2, bh2, out);
}

// round 8
// speedup vs baseline: 2.3579x; 1.0314x over previous
#include <cuda_runtime.h>
#include <cuda_bf16.h>
#include <math.h>
#include <stdint.h>

// ----------------------------------------------------------------------------
// IGNN / EGNN layer, GB300 (sm_103a built as sm_103 -> mma.sync, no tcgen05).
// Round 8: edge kernel epilogue -> red.global.add.v4.f32 via lane-pair shfl
// (halves atomic instruction count), B fragments via ldmatrix.x4 nt-pairs
// (halves B LDSM count). Node kernels unchanged from R7 (HMMA).
// ----------------------------------------------------------------------------

#define NN 50000
#define NE 800000
#define DH 128
#define DE 16
#define DM 128

__device__ __align__(16) float g_Ha[(size_t)NN * DM];
__device__ __align__(16) float g_Hb[(size_t)NN * DM];
__device__ __align__(16) float g_msg[(size_t)NN * DM];

__device__ __forceinline__ float fsigmoid(float v) {
    return 1.0f / (1.0f + __expf(-v));
}

__device__ __forceinline__ void fma8x2(float a0c[8], float a1c[8], float a0, float a1,
                                       const float* __restrict__ w) {
    float4 w0 = *(const float4*)(w);
    float4 w1 = *(const float4*)(w + 4);
    a0c[0] += a0 * w0.x; a1c[0] += a1 * w0.x;
    a0c[1] += a0 * w0.y; a1c[1] += a1 * w0.y;
    a0c[2] += a0 * w0.z; a1c[2] += a1 * w0.z;
    a0c[3] += a0 * w0.w; a1c[3] += a1 * w0.w;
    a0c[4] += a0 * w1.x; a1c[4] += a1 * w1.x;
    a0c[5] += a0 * w1.y; a1c[5] += a1 * w1.y;
    a0c[6] += a0 * w1.z; a1c[6] += a1 * w1.z;
    a0c[7] += a0 * w1.w; a1c[7] += a1 * w1.w;
}

__device__ __forceinline__ uint32_t smem_to_u32(const void* smem_ptr) {
    uint32_t addr;
    asm("{ .reg .u64 tmp; cvta.to.shared.u64 tmp, %1; cvt.u32.u64 %0, tmp; }"
        : "=r"(addr) : "l"(smem_ptr));
    return addr;
}

__device__ __forceinline__ void ldmatrix_x4(uint32_t& r0, uint32_t& r1,
                                            uint32_t& r2, uint32_t& r3, uint32_t addr) {
    asm volatile("ldmatrix.sync.aligned.m8n8.x4.shared.b16 {%0,%1,%2,%3}, [%4];"
                 : "=r"(r0), "=r"(r1), "=r"(r2), "=r"(r3) : "r"(addr));
}
__device__ __forceinline__ void ldmatrix_x2(uint32_t& r0, uint32_t& r1, uint32_t addr) {
    asm volatile("ldmatrix.sync.aligned.m8n8.x2.shared.b16 {%0,%1}, [%2];"
                 : "=r"(r0), "=r"(r1) : "r"(addr));
}
__device__ __forceinline__ void mma_bf16(float d[4], const uint32_t a[4],
                                         const uint32_t b[2], const float c[4]) {
    asm volatile(
        "mma.sync.aligned.m16n8k16.row.col.f32.bf16.bf16.f32 "
        "{%0,%1,%2,%3}, {%4,%5,%6,%7}, {%8,%9}, {%10,%11,%12,%13};"
        : "=f"(d[0]), "=f"(d[1]), "=f"(d[2]), "=f"(d[3])
        : "r"(a[0]), "r"(a[1]), "r"(a[2]), "r"(a[3]),
          "r"(b[0]), "r"(b[1]),
          "f"(c[0]), "f"(c[1]), "f"(c[2]), "f"(c[3]));
}
__device__ __forceinline__ void red_v4(float* addr, float v0, float v1, float v2, float v3) {
    asm volatile("red.global.add.v4.f32 [%0], {%1, %2, %3, %4};"
                 :: "l"(addr), "f"(v0), "f"(v1), "f"(v2), "f"(v3) : "memory");
}

// pack float4 -> two bf16x2 words
__device__ __forceinline__ uint2 pack_bf16x4(float4 v) {
    __nv_bfloat162 lo = __floats2bfloat162_rn(v.x, v.y);
    __nv_bfloat162 hi = __floats2bfloat162_rn(v.z, v.w);
    uint2 r;
    r.x = *(uint32_t*)&lo;
    r.y = *(uint32_t*)&hi;
    return r;
}

// ---------------------------------------------------------------------------
__global__ void zero_msg_kernel() {
    size_t i = (size_t)blockIdx.x * blockDim.x + threadIdx.x;
    size_t n4 = (size_t)NN * DM / 4;
    if (i < n4) ((float4*)g_msg)[i] = make_float4(0.f, 0.f, 0.f, 0.f);
}

// ---------------------------------------------------------------------------
// kernel 1 (HMMA): Ha = h @ W1a^T, Hb = h @ W1b^T.  (unchanged from R7)
// ---------------------------------------------------------------------------
#define NP_A   0
#define NP_WA  34816
#define NP_WB  69632
#define NP_TOTAL 104448
#define RS 272

__global__ void __launch_bounds__(256, 2)
node_pre_kernel(const float* __restrict__ h, const float* __restrict__ We1) {
    extern __shared__ __align__(16) char smraw[];
    const uint32_t smem_u32 = smem_to_u32(smraw);
    const int tid  = threadIdx.x;
    const int warp = tid >> 5;
    const int lane = tid & 31;

    for (int idx = tid; idx < 128 * 128; idx += 256) {
        int n = idx >> 7, k = idx & 127;
        *(__nv_bfloat16*)(smraw + NP_WA + n * RS + k * 2) =
            __float2bfloat16(We1[n * 273 + k]);
        *(__nv_bfloat16*)(smraw + NP_WB + n * RS + k * 2) =
            __float2bfloat16(We1[n * 273 + 128 + k]);
    }
    __syncthreads();

    const int m0 = warp * 16;
    const int arow = m0 + (lane & 7) + ((lane >> 3) & 1) * 8;
    const uint32_t a_base  = smem_u32 + NP_A + (uint32_t)arow * RS + ((lane >> 4) & 1) * 16;
    const int bl = lane & 15;
    const uint32_t ba_base = smem_u32 + NP_WA + (uint32_t)(bl & 7) * RS + ((bl >> 3) & 1) * 16;
    const uint32_t bb_base = smem_u32 + NP_WB + (uint32_t)(bl & 7) * RS + ((bl >> 3) & 1) * 16;

    const int tig = lane & 3, grp = lane >> 2;
    const int ntiles = (NN + 127) / 128;

    for (int tile = blockIdx.x; tile < ntiles; tile += gridDim.x) {
        const int base = tile * 128;
        __syncthreads();
        for (int idx = tid; idx < 128 * 32; idx += 256) {
            int r = idx >> 5, j4 = (idx & 31) * 4;
            int node = base + r;
            float4 v = (node < NN) ? *(const float4*)&h[(size_t)node * DH + j4]
                                   : make_float4(0.f, 0.f, 0.f, 0.f);
            *(uint2*)(smraw + NP_A + r * RS + j4 * 2) = pack_bf16x4(v);
        }
        __syncthreads();

        const int node0 = base + m0 + grp;
        const int node1 = node0 + 8;

        {
            float acc[16][4];
#pragma unroll
            for (int nt = 0; nt < 16; nt++)
#pragma unroll
                for (int r = 0; r < 4; r++) acc[nt][r] = 0.f;
#pragma unroll
            for (int k = 0; k < 8; k++) {
                uint32_t a[4];
                ldmatrix_x4(a[0], a[1], a[2], a[3], a_base + (uint32_t)k * 32);
#pragma unroll
                for (int nt = 0; nt < 16; nt++) {
                    uint32_t b[2];
                    ldmatrix_x2(b[0], b[1], ba_base + (uint32_t)nt * (8 * RS) + (uint32_t)k * 32);
                    mma_bf16(acc[nt], a, b, acc[nt]);
                }
            }
#pragma unroll
            for (int nt = 0; nt < 16; nt++) {
                const int c0 = nt * 8 + tig * 2;
                if (node0 < NN) *(float2*)&g_Ha[(size_t)node0 * DM + c0] =
                    make_float2(acc[nt][0], acc[nt][1]);
                if (node1 < NN) *(float2*)&g_Ha[(size_t)node1 * DM + c0] =
                    make_float2(acc[nt][2], acc[nt][3]);
            }
        }
        {
            float acc[16][4];
#pragma unroll
            for (int nt = 0; nt < 16; nt++)
#pragma unroll
                for (int r = 0; r < 4; r++) acc[nt][r] = 0.f;
#pragma unroll
            for (int k = 0; k < 8; k++) {
                uint32_t a[4];
                ldmatrix_x4(a[0], a[1], a[2], a[3], a_base + (uint32_t)k * 32);
#pragma unroll
                for (int nt = 0; nt < 16; nt++) {
                    uint32_t b[2];
                    ldmatrix_x2(b[0], b[1], bb_base + (uint32_t)nt * (8 * RS) + (uint32_t)k * 32);
                    mma_bf16(acc[nt], a, b, acc[nt]);
                }
            }
#pragma unroll
            for (int nt = 0; nt < 16; nt++) {
                const int c0 = nt * 8 + tig * 2;
                if (node0 < NN) *(float2*)&g_Hb[(size_t)node0 * DM + c0] =
                    make_float2(acc[nt][0], acc[nt][1]);
                if (node1 < NN) *(float2*)&g_Hb[(size_t)node1 * DM + c0] =
                    make_float2(acc[nt][2], acc[nt][3]);
            }
        }
    }
}

// ---------------------------------------------------------------------------
// kernel 2: edge kernel, HMMA stage 2 + v4 reduction scatter.
// ---------------------------------------------------------------------------
#define EB_M1    0
#define EB_W2    34816
#define EB_W1ET  69632
#define EB_WR    77824
#define EB_BE1   78336
#define EB_BE2   78848
#define EB_WAS   79360
#define EB_EAS   79872
#define EB_RAD   88576
#define EB_SROW  89088
#define EB_SCOL  89600
#define EB_TOTAL 90112

#define M1_STRIDE 272

__global__ void __launch_bounds__(256, 2)
edge_kernel(const float* __restrict__ x,
            const float* __restrict__ edge_attr,
            const float* __restrict__ We1,
            const float* __restrict__ be1,
            const float* __restrict__ We2,
            const float* __restrict__ be2,
            const float* __restrict__ Wa,
            const float* __restrict__ ba,
            const int* __restrict__ ei) {
    extern __shared__ __align__(16) char smraw[];
    float* W1eT = (float*)(smraw + EB_W1ET);
    float* Wr   = (float*)(smraw + EB_WR);
    float* be1s = (float*)(smraw + EB_BE1);
    float* be2s = (float*)(smraw + EB_BE2);
    float* Was  = (float*)(smraw + EB_WAS);
    float* eas  = (float*)(smraw + EB_EAS);
    float* radS = (float*)(smraw + EB_RAD);
    int*   srow = (int*)(smraw + EB_SROW);
    int*   scol = (int*)(smraw + EB_SCOL);

    const uint32_t smem_u32 = smem_to_u32(smraw);
    const int tid  = threadIdx.x;
    const int warp = tid >> 5;
    const int lane = tid & 31;

    for (int idx = tid; idx < 128 * 128; idx += 256) {
        int n = idx >> 7, k = idx & 127;
        *(__nv_bfloat16*)(smraw + EB_W2 + n * M1_STRIDE + k * 2) =
            __float2bfloat16(We2[n * 128 + k]);
    }
    for (int idx = tid; idx < 16 * 128; idx += 256) {
        int t = idx >> 7, k = idx & 127;
        W1eT[t * 128 + k] = We1[k * 273 + 257 + t];
    }
    for (int k = tid; k < 128; k += 256) {
        Wr[k]   = We1[k * 273 + 256];
        be1s[k] = be1[k];
        be2s[k] = be2[k];
        Was[k]  = Wa[k];
    }
    const float ba0 = ba[0];
    __syncthreads();

    const int m0 = warp * 16;
    const int arow = m0 + (lane & 7) + ((lane >> 3) & 1) * 8;
    const uint32_t a_base = smem_u32 + EB_M1 + (uint32_t)arow * M1_STRIDE
                          + ((lane >> 4) & 1) * 16;
    // B x4 nt-pair base: lanes 0-7 (nt0,k0), 8-15 (nt0,k0+8), 16-23 (nt1,k0), 24-31 (nt1,k0+8)
    const uint32_t b4_base = smem_u32 + EB_W2
                           + (uint32_t)((lane & 7) + ((lane >> 4) & 1) * 8) * M1_STRIDE
                           + ((lane >> 3) & 1) * 16;

    const int g = tid >> 4, e0b = tid & 15, k0c = g * 8;
    const int tig = lane & 3, grp = lane >> 2;
    const int jj = tig >> 1;            // which 4-col group within the 8-col nt tile
    const bool isOdd = (tig & 1) != 0;  // odd lane of the shfl pair handles row1

    for (int tile = blockIdx.x; tile < NE / 128; tile += gridDim.x) {
        const int base = tile * 128;
        __syncthreads();

        if (tid < 128) {
            int r = ei[base + tid];
            int c = ei[NE + base + tid];
            srow[tid] = r;
            scol[tid] = c;
            float dx = x[(size_t)r * 3 + 0] - x[(size_t)c * 3 + 0];
            float dy = x[(size_t)r * 3 + 1] - x[(size_t)c * 3 + 1];
            float dz = x[(size_t)r * 3 + 2] - x[(size_t)c * 3 + 2];
            radS[tid] = sqrtf(dx * dx + dy * dy + dz * dz);
        }
        for (int idx = tid; idx < 128 * 16; idx += 256) {
            int ee = idx >> 4, t = idx & 15;
            eas[ee * 17 + t] = edge_attr[(size_t)(base + ee) * DE + t];
        }
        __syncthreads();

        // ---- stage 1 ----
#pragma unroll
        for (int s = 0; s < 4; s++) {
            const int le0 = s * 32 + e0b;
            const int le1 = le0 + 16;
            const int row0 = srow[le0], col0 = scol[le0];
            const int row1 = srow[le1], col1 = scol[le1];
            const float rad0 = radS[le0], rad1 = radS[le1];

            float acc0[8], acc1[8];
            {
                const float4* pHa0 = (const float4*)(g_Ha + (size_t)row0 * DM + k0c);
                const float4* pHb0 = (const float4*)(g_Hb + (size_t)col0 * DM + k0c);
                const float4* pHa1 = (const float4*)(g_Ha + (size_t)row1 * DM + k0c);
                const float4* pHb1 = (const float4*)(g_Hb + (size_t)col1 * DM + k0c);
                float4 a00 = pHa0[0], a01 = pHa0[1], b00 = pHb0[0], b01 = pHb0[1];
                float4 a10 = pHa1[0], a11 = pHa1[1], b10 = pHb1[0], b11 = pHb1[1];
                acc0[0] = a00.x + b00.x; acc0[1] = a00.y + b00.y;
                acc0[2] = a00.z + b00.z; acc0[3] = a00.w + b00.w;
                acc0[4] = a01.x + b01.x; acc0[5] = a01.y + b01.y;
                acc0[6] = a01.z + b01.z; acc0[7] = a01.w + b01.w;
                acc1[0] = a10.x + b10.x; acc1[1] = a10.y + b10.y;
                acc1[2] = a10.z + b10.z; acc1[3] = a10.w + b10.w;
                acc1[4] = a11.x + b11.x; acc1[5] = a11.y + b11.y;
                acc1[6] = a11.z + b11.z; acc1[7] = a11.w + b11.w;
#pragma unroll
                for (int r = 0; r < 8; r++) {
                    float bb = be1s[k0c + r], wr = Wr[k0c + r];
                    acc0[r] += bb + rad0 * wr;
                    acc1[r] += bb + rad1 * wr;
                }
            }
#pragma unroll
            for (int t = 0; t < 16; t++) {
                float a0 = eas[le0 * 17 + t];
                float a1 = eas[le1 * 17 + t];
                fma8x2(acc0, acc1, a0, a1, W1eT + t * 128 + k0c);
            }
            uint32_t p0[4], p1[4];
#pragma unroll
            for (int r = 0; r < 4; r++) {
                float v00 = acc0[2 * r], v01 = acc0[2 * r + 1];
                float v10 = acc1[2 * r], v11 = acc1[2 * r + 1];
                __nv_bfloat162 q0 = __floats2bfloat162_rn(v00 * fsigmoid(v00), v01 * fsigmoid(v01));
                __nv_bfloat162 q1 = __floats2bfloat162_rn(v10 * fsigmoid(v10), v11 * fsigmoid(v11));
                p0[r] = *(uint32_t*)&q0;
                p1[r] = *(uint32_t*)&q1;
            }
            *(uint4*)(smraw + EB_M1 + le0 * M1_STRIDE + k0c * 2) =
                make_uint4(p0[0], p0[1], p0[2], p0[3]);
            *(uint4*)(smraw + EB_M1 + le1 * M1_STRIDE + k0c * 2) =
                make_uint4(p1[0], p1[1], p1[2], p1[3]);
        }
        __syncthreads();

        // ---- stage 2: HMMA (B via x4 nt-pairs) ----
        float acc[16][4];
#pragma unroll
        for (int nt = 0; nt < 16; nt++)
#pragma unroll
            for (int r = 0; r < 4; r++) acc[nt][r] = 0.f;

#pragma unroll
        for (int k = 0; k < 8; k++) {
            uint32_t a[4];
            ldmatrix_x4(a[0], a[1], a[2], a[3], a_base + (uint32_t)k * 32);
#pragma unroll
            for (int ntp = 0; ntp < 8; ntp++) {
                uint32_t b4[4];
                ldmatrix_x4(b4[0], b4[1], b4[2], b4[3],
                            b4_base + (uint32_t)ntp * (16 * M1_STRIDE) + (uint32_t)k * 32);
                mma_bf16(acc[2 * ntp],     a, b4,     acc[2 * ntp]);
                mma_bf16(acc[2 * ntp + 1], a, b4 + 2, acc[2 * ntp + 1]);
            }
        }

        // ---- epilogue ----
        float pr0 = 0.f, pr1 = 0.f;
#pragma unroll
        for (int nt = 0; nt < 16; nt++) {
            const int c0 = nt * 8 + tig * 2;
            float2 bb = *(float2*)&be2s[c0];
            float2 wa = *(float2*)&Was[c0];
            float v0 = acc[nt][0] + bb.x;
            float v1 = acc[nt][1] + bb.y;
            float v2 = acc[nt][2] + bb.x;
            float v3 = acc[nt][3] + bb.y;
            float s0 = v0 * fsigmoid(v0);
            float s1 = v1 * fsigmoid(v1);
            float s2 = v2 * fsigmoid(v2);
            float s3 = v3 * fsigmoid(v3);
            acc[nt][0] = s0; acc[nt][1] = s1; acc[nt][2] = s2; acc[nt][3] = s3;
            pr0 += s0 * wa.x + s1 * wa.y;
            pr1 += s2 * wa.x + s3 * wa.y;
        }
        pr0 += __shfl_xor_sync(0xFFFFFFFF, pr0, 1);
        pr0 += __shfl_xor_sync(0xFFFFFFFF, pr0, 2);
        pr1 += __shfl_xor_sync(0xFFFFFFFF, pr1, 1);
        pr1 += __shfl_xor_sync(0xFFFFFFFF, pr1, 2);
        const float att0 = fsigmoid(pr0 + ba0);
        const float att1 = fsigmoid(pr1 + ba0);

        const int node0 = srow[m0 + grp];
        const int node1 = srow[m0 + grp + 8];
        // lane-pair (shfl.xor 1): even lane scatters row0's 4 contiguous cols,
        // odd lane scatters row1's. attm/dst selected per parity.
        const float attm = isOdd ? att1 : att0;
        float* dst = g_msg + (size_t)(isOdd ? node1 : node0) * DM + jj * 4;
#pragma unroll
        for (int nt = 0; nt < 16; nt++) {
            float s0 = acc[nt][0], s1 = acc[nt][1];
            float s2 = acc[nt][2], s3 = acc[nt][3];
            float q0 = __shfl_xor_sync(0xFFFFFFFF, s0, 1);
            float q1 = __shfl_xor_sync(0xFFFFFFFF, s1, 1);
            float q2 = __shfl_xor_sync(0xFFFFFFFF, s2, 1);
            float q3 = __shfl_xor_sync(0xFFFFFFFF, s3, 1);
            // even lane (tig even): row0 = (s0, s1, partner.s0, partner.s1)
            // odd  lane (tig odd) : row1 = (partner.s2, partner.s3, s2, s3)
            float v0 = isOdd ? q2 : s0;
            float v1 = isOdd ? q3 : s1;
            float v2 = isOdd ? s2 : q0;
            float v3 = isOdd ? s3 : q1;
            red_v4(dst + nt * 8, v0 * attm, v1 * attm, v2 * attm, v3 * attm);
        }
    }
}

// ---------------------------------------------------------------------------
// kernel 3 (HMMA): node post.  (unchanged from R7)
// ---------------------------------------------------------------------------
#define PO_A   0
#define PO_W1  67584
#define PO_W2  135168
#define PO_U   169984
#define PO_B1  204800
#define PO_B2  205312
#define PO_TOTAL 205824
#define RS2 528

__global__ void __launch_bounds__(256, 1)
node_post_kernel(const float* __restrict__ h,
                 const float* __restrict__ Wh1,
                 const float* __restrict__ bh1,
                 const float* __restrict__ Wh2,
                 const float* __restrict__ bh2,
                 float* __restrict__ out) {
    extern __shared__ __align__(16) char smraw[];
    float* b1s = (float*)(smraw + PO_B1);
    float* b2s = (float*)(smraw + PO_B2);

    const uint32_t smem_u32 = smem_to_u32(smraw);
    const int tid  = threadIdx.x;
    const int warp = tid >> 5;
    const int lane = tid & 31;

    for (int idx = tid; idx < 128 * 64; idx += 256) {
        int n = idx >> 6, k4 = (idx & 63) * 4;
        float4 v = *(const float4*)&Wh1[(size_t)n * 256 + k4];
        *(uint2*)(smraw + PO_W1 + n * RS2 + k4 * 2) = pack_bf16x4(v);
    }
    for (int idx = tid; idx < 128 * 32; idx += 256) {
        int n = idx >> 5, k4 = (idx & 31) * 4;
        float4 v = *(const float4*)&Wh2[(size_t)n * 128 + k4];
        *(uint2*)(smraw + PO_W2 + n * RS + k4 * 2) = pack_bf16x4(v);
    }
    for (int k = tid; k < 128; k += 256) {
        b1s[k] = bh1[k];
        b2s[k] = bh2[k];
    }
    __syncthreads();

    const int m0 = warp * 16;
    const int arow = m0 + (lane & 7) + ((lane >> 3) & 1) * 8;
    const uint32_t a1_base = smem_u32 + PO_A + (uint32_t)arow * RS2 + ((lane >> 4) & 1) * 16;
    const uint32_t a2_base = smem_u32 + PO_U + (uint32_t)arow * RS  + ((lane >> 4) & 1) * 16;
    const int bl = lane & 15;
    const uint32_t b1_base = smem_u32 + PO_W1 + (uint32_t)(bl & 7) * RS2 + ((bl >> 3) & 1) * 16;
    const uint32_t b2_base = smem_u32 + PO_W2 + (uint32_t)(bl & 7) * RS  + ((bl >> 3) & 1) * 16;

    const int tig = lane & 3, grp = lane >> 2;
    const int ntiles = (NN + 127) / 128;

    for (int tile = blockIdx.x; tile < ntiles; tile += gridDim.x) {
        const int base = tile * 128;
        __syncthreads();
        for (int idx = tid; idx < 128 * 32; idx += 256) {
            int r = idx >> 5, j4 = (idx & 31) * 4;
            int node = base + r;
            float4 vh = (node < NN) ? *(const float4*)&h[(size_t)node * DH + j4]
                                    : make_float4(0.f, 0.f, 0.f, 0.f);
            float4 vm = (node < NN) ? *(const float4*)&g_msg[(size_t)node * DM + j4]
                                    : make_float4(0.f, 0.f, 0.f, 0.f);
            *(uint2*)(smraw + PO_A + r * RS2 + j4 * 2)         = pack_bf16x4(vh);
            *(uint2*)(smraw + PO_A + r * RS2 + 256 + j4 * 2)   = pack_bf16x4(vm);
        }
        __syncthreads();

        float acc[16][4];
#pragma unroll
        for (int nt = 0; nt < 16; nt++)
#pragma unroll
            for (int r = 0; r < 4; r++) acc[nt][r] = 0.f;
#pragma unroll
        for (int k = 0; k < 16; k++) {
            uint32_t a[4];
            ldmatrix_x4(a[0], a[1], a[2], a[3], a1_base + (uint32_t)k * 32);
#pragma unroll
            for (int nt = 0; nt < 16; nt++) {
                uint32_t b[2];
                ldmatrix_x2(b[0], b[1], b1_base + (uint32_t)nt * (8 * RS2) + (uint32_t)k * 32);
                mma_bf16(acc[nt], a, b, acc[nt]);
            }
        }
#pragma unroll
        for (int nt = 0; nt < 16; nt++) {
            const int c0 = nt * 8 + tig * 2;
            float2 bb = *(float2*)&b1s[c0];
            float v0 = acc[nt][0] + bb.x;
            float v1 = acc[nt][1] + bb.y;
            float v2 = acc[nt][2] + bb.x;
            float v3 = acc[nt][3] + bb.y;
            __nv_bfloat162 q0 = __floats2bfloat162_rn(v0 * fsigmoid(v0), v1 * fsigmoid(v1));
            __nv_bfloat162 q1 = __floats2bfloat162_rn(v2 * fsigmoid(v2), v3 * fsigmoid(v3));
            *(uint32_t*)(smraw + PO_U + (m0 + grp) * RS + c0 * 2)     = *(uint32_t*)&q0;
            *(uint32_t*)(smraw + PO_U + (m0 + grp + 8) * RS + c0 * 2) = *(uint32_t*)&q1;
        }
        __syncthreads();

#pragma unroll
        for (int nt = 0; nt < 16; nt++)
#pragma unroll
            for (int r = 0; r < 4; r++) acc[nt][r] = 0.f;
#pragma unroll
        for (int k = 0; k < 8; k++) {
            uint32_t a[4];
            ldmatrix_x4(a[0], a[1], a[2], a[3], a2_base + (uint32_t)k * 32);
#pragma unroll
            for (int nt = 0; nt < 16; nt++) {
                uint32_t b[2];
                ldmatrix_x2(b[0], b[1], b2_base + (uint32_t)nt * (8 * RS) + (uint32_t)k * 32);
                mma_bf16(acc[nt], a, b, acc[nt]);
            }
        }

        const int node0 = base + m0 + grp;
        const int node1 = node0 + 8;
#pragma unroll
        for (int nt = 0; nt < 16; nt++) {
            const int c0 = nt * 8 + tig * 2;
            float2 bb = *(float2*)&b2s[c0];
            if (node0 < NN) {
                float2 hv = *(const float2*)&h[(size_t)node0 * DH + c0];
                *(float2*)&out[(size_t)node0 * DH + c0] =
                    make_float2(hv.x + acc[nt][0] + bb.x, hv.y + acc[nt][1] + bb.y);
            }
            if (node1 < NN) {
                float2 hv = *(const float2*)&h[(size_t)node1 * DH + c0];
                *(float2*)&out[(size_t)node1 * DH + c0] =
                    make_float2(hv.x + acc[nt][2] + bb.x, hv.y + acc[nt][3] + bb.y);
            }
        }
    }
}

// ---------------------------------------------------------------------------
extern "C" void kernel_launch(void* const* d_in, const int* in_sizes, int n_in,
                              void* d_out, int out_size) {
    const float* x   = (const float*)d_in[0];
    const float* h   = (const float*)d_in[1];
    const float* ea  = (const float*)d_in[2];
    const float* We1 = (const float*)d_in[3];
    const float* be1 = (const float*)d_in[4];
    const float* We2 = (const float*)d_in[5];
    const float* be2 = (const float*)d_in[6];
    const float* Wh1 = (const float*)d_in[7];
    const float* bh1 = (const float*)d_in[8];
    const float* Wh2 = (const float*)d_in[9];
    const float* bh2 = (const float*)d_in[10];
    const float* Wa  = (const float*)d_in[11];
    const float* ba  = (const float*)d_in[12];
    const int*   ei  = (const int*)d_in[13];   // int32
    float* out = (float*)d_out;

    cudaFuncSetAttribute(node_pre_kernel,
                         cudaFuncAttributeMaxDynamicSharedMemorySize, NP_TOTAL);
    cudaFuncSetAttribute(edge_kernel,
                         cudaFuncAttributeMaxDynamicSharedMemorySize, EB_TOTAL);
    cudaFuncSetAttribute(node_post_kernel,
                         cudaFuncAttributeMaxDynamicSharedMemorySize, PO_TOTAL);

    zero_msg_kernel<<<(NN * DM / 4 + 255) / 256, 256>>>();
    node_pre_kernel<<<296, 256, NP_TOTAL>>>(h, We1);
    edge_kernel<<<296, 256, EB_TOTAL>>>(x, ea, We1, be1, We2, be2, Wa, ba, ei);
    node_post_kernel<<<148, 256, PO_TOTAL>>>(h, Wh1, bh1, Wh2, bh2, out);
}